// round 1
// baseline (speedup 1.0000x reference)
#include <cuda_runtime.h>
#include <math.h>

// ---------------------------------------------------------------------------
// Shapes (compile-time constants for this problem instance)
// ---------------------------------------------------------------------------
#define BATCH   2048
#define NTOK    64
#define DIM     192
#define HEADS   6
#define HD      32        // DIM / HEADS
#define QKVC    576       // 3*DIM
#define NPOS    343       // 7*7*7
#define CPBH    512
#define NW      64        // mask windows

// ---------------------------------------------------------------------------
// Scratch (static device memory; cudaMalloc is forbidden)
// ---------------------------------------------------------------------------
// qkv laid out as [b][which(3)][h(6)][n(64)][d(32)]
__device__ float g_qkv[(size_t)BATCH * 3 * HEADS * NTOK * HD];   // ~302 MB
// attention output, heads-major concat: [b][n][h*32+d]  (= proj GEMM input)
__device__ float g_attn[(size_t)BATCH * NTOK * DIM];             // ~100 MB
__device__ float g_table[NPOS * HEADS];                          // CPB MLP out
__device__ float g_bias[HEADS * NTOK * NTOK];                    // gathered bias

// ---------------------------------------------------------------------------
// Kernel 1: CPB MLP  table[p][h] = sum_j relu(rpb[p]·w1[j]+b1[j]) * w2[h][j]
// ---------------------------------------------------------------------------
__global__ void cpb_table_kernel(const float* __restrict__ rpb,
                                 const float* __restrict__ w1,
                                 const float* __restrict__ b1,
                                 const float* __restrict__ w2)
{
    int idx = blockIdx.x * blockDim.x + threadIdx.x;
    if (idx >= NPOS * HEADS) return;
    int p = idx / HEADS, h = idx % HEADS;
    float r0 = rpb[p * 3 + 0], r1 = rpb[p * 3 + 1], r2 = rpb[p * 3 + 2];
    float acc = 0.f;
#pragma unroll 4
    for (int j = 0; j < CPBH; ++j) {
        float hv = fmaf(w1[j * 3 + 0], r0,
                   fmaf(w1[j * 3 + 1], r1,
                   fmaf(w1[j * 3 + 2], r2, b1[j])));
        hv = fmaxf(hv, 0.f);
        acc = fmaf(hv, w2[h * CPBH + j], acc);
    }
    g_table[p * HEADS + h] = acc;
}

// ---------------------------------------------------------------------------
// Kernel 2: bias gather: bias[h][i][j] = 16*sigmoid(table[rpb_idx[i][j]][h])
// ---------------------------------------------------------------------------
__global__ void bias_gather_kernel(const int* __restrict__ rpb_idx)
{
    int idx = blockIdx.x * blockDim.x + threadIdx.x;
    if (idx >= HEADS * NTOK * NTOK) return;
    int h = idx / (NTOK * NTOK);
    int ij = idx % (NTOK * NTOK);
    int p = rpb_idx[ij];
    float t = g_table[p * HEADS + h];
    g_bias[idx] = 16.f / (1.f + expf(-t));
}

// ---------------------------------------------------------------------------
// Tiled fp32 GEMM:  C[r][c] = sum_k A[r][k] * W[c][k] + bias[c]
// BM=BN=64, BK=16, 256 threads, 4x4 register tile.
// ---------------------------------------------------------------------------
#define BK 16

// QKV GEMM: A = x (131072 x 192), W = qkv_w (576 x 192).
// Output scattered into g_qkv layout.
__global__ void qkv_gemm_kernel(const float* __restrict__ A,
                                const float* __restrict__ W,
                                const float* __restrict__ bias)
{
    __shared__ __align__(16) float As[BK][68];
    __shared__ __align__(16) float Ws[BK][68];

    const int by = blockIdx.x;      // window / row-tile (0..2047)
    const int bx = blockIdx.y;      // col tile (0..8)
    const int tid = threadIdx.x;
    const int tx = tid & 15, ty = tid >> 4;
    const int rowBase = by * 64;
    const int colBase = bx * 64;

    float acc[4][4] = {};

    for (int k0 = 0; k0 < DIM; k0 += BK) {
#pragma unroll
        for (int i = 0; i < 4; ++i) {
            int e = tid + i * 256;
            int r = e >> 4, kk = e & 15;
            As[kk][r] = A[(size_t)(rowBase + r) * DIM + k0 + kk];
            Ws[kk][r] = W[(size_t)(colBase + r) * DIM + k0 + kk];
        }
        __syncthreads();
#pragma unroll
        for (int kk = 0; kk < BK; ++kk) {
            float4 a = *(const float4*)&As[kk][ty * 4];
            float4 b = *(const float4*)&Ws[kk][tx * 4];
            acc[0][0] = fmaf(a.x, b.x, acc[0][0]);
            acc[0][1] = fmaf(a.x, b.y, acc[0][1]);
            acc[0][2] = fmaf(a.x, b.z, acc[0][2]);
            acc[0][3] = fmaf(a.x, b.w, acc[0][3]);
            acc[1][0] = fmaf(a.y, b.x, acc[1][0]);
            acc[1][1] = fmaf(a.y, b.y, acc[1][1]);
            acc[1][2] = fmaf(a.y, b.z, acc[1][2]);
            acc[1][3] = fmaf(a.y, b.w, acc[1][3]);
            acc[2][0] = fmaf(a.z, b.x, acc[2][0]);
            acc[2][1] = fmaf(a.z, b.y, acc[2][1]);
            acc[2][2] = fmaf(a.z, b.z, acc[2][2]);
            acc[2][3] = fmaf(a.z, b.w, acc[2][3]);
            acc[3][0] = fmaf(a.w, b.x, acc[3][0]);
            acc[3][1] = fmaf(a.w, b.y, acc[3][1]);
            acc[3][2] = fmaf(a.w, b.z, acc[3][2]);
            acc[3][3] = fmaf(a.w, b.w, acc[3][3]);
        }
        __syncthreads();
    }

    // scatter into g_qkv[b][which][h][n][d]
    const int b = by;
#pragma unroll
    for (int i = 0; i < 4; ++i) {
        int n = ty * 4 + i;
#pragma unroll
        for (int j = 0; j < 4; ++j) {
            int c = colBase + tx * 4 + j;
            int which = c / DIM;
            int rem = c - which * DIM;
            int h = rem >> 5;
            int d = rem & 31;
            size_t idx = ((((size_t)b * 3 + which) * HEADS + h) * NTOK + n) * HD + d;
            g_qkv[idx] = acc[i][j] + bias[c];
        }
    }
}

// Proj GEMM: A = g_attn (131072 x 192), W = proj_w (192 x 192) -> d_out.
__global__ void proj_gemm_kernel(const float* __restrict__ W,
                                 const float* __restrict__ bias,
                                 float* __restrict__ out)
{
    __shared__ __align__(16) float As[BK][68];
    __shared__ __align__(16) float Ws[BK][68];

    const int by = blockIdx.x;      // row tile (0..2047)
    const int bx = blockIdx.y;      // col tile (0..2)
    const int tid = threadIdx.x;
    const int tx = tid & 15, ty = tid >> 4;
    const int rowBase = by * 64;
    const int colBase = bx * 64;

    float acc[4][4] = {};

    for (int k0 = 0; k0 < DIM; k0 += BK) {
#pragma unroll
        for (int i = 0; i < 4; ++i) {
            int e = tid + i * 256;
            int r = e >> 4, kk = e & 15;
            As[kk][r] = g_attn[(size_t)(rowBase + r) * DIM + k0 + kk];
            Ws[kk][r] = W[(size_t)(colBase + r) * DIM + k0 + kk];
        }
        __syncthreads();
#pragma unroll
        for (int kk = 0; kk < BK; ++kk) {
            float4 a = *(const float4*)&As[kk][ty * 4];
            float4 b = *(const float4*)&Ws[kk][tx * 4];
            acc[0][0] = fmaf(a.x, b.x, acc[0][0]);
            acc[0][1] = fmaf(a.x, b.y, acc[0][1]);
            acc[0][2] = fmaf(a.x, b.z, acc[0][2]);
            acc[0][3] = fmaf(a.x, b.w, acc[0][3]);
            acc[1][0] = fmaf(a.y, b.x, acc[1][0]);
            acc[1][1] = fmaf(a.y, b.y, acc[1][1]);
            acc[1][2] = fmaf(a.y, b.z, acc[1][2]);
            acc[1][3] = fmaf(a.y, b.w, acc[1][3]);
            acc[2][0] = fmaf(a.z, b.x, acc[2][0]);
            acc[2][1] = fmaf(a.z, b.y, acc[2][1]);
            acc[2][2] = fmaf(a.z, b.z, acc[2][2]);
            acc[2][3] = fmaf(a.z, b.w, acc[2][3]);
            acc[3][0] = fmaf(a.w, b.x, acc[3][0]);
            acc[3][1] = fmaf(a.w, b.y, acc[3][1]);
            acc[3][2] = fmaf(a.w, b.z, acc[3][2]);
            acc[3][3] = fmaf(a.w, b.w, acc[3][3]);
        }
        __syncthreads();
    }

#pragma unroll
    for (int i = 0; i < 4; ++i) {
        int r = rowBase + ty * 4 + i;
#pragma unroll
        for (int j = 0; j < 4; ++j) {
            int c = colBase + tx * 4 + j;
            out[(size_t)r * DIM + c] = acc[i][j] + bias[c];
        }
    }
}

// ---------------------------------------------------------------------------
// Kernel 4: per-(window, head) cosine attention + softmax + P@V
// block = 256 threads, grid = (2048, 6)
// ---------------------------------------------------------------------------
__global__ void attn_kernel(const float* __restrict__ logit_scale,
                            const float* __restrict__ mask)
{
    __shared__ __align__(16) float qs[HD][68];   // [d][n]
    __shared__ __align__(16) float ks[HD][68];   // [d][n]
    __shared__ float vs[NTOK][33];               // [m][d]
    __shared__ float S[NTOK][65];                // scores
    __shared__ float invq[NTOK], invk[NTOK];

    const int b = blockIdx.x;
    const int h = blockIdx.y;
    const int tid = threadIdx.x;

    const float* qp = g_qkv + ((((size_t)b * 3 + 0) * HEADS + h) * NTOK) * HD;
    const float* kp = g_qkv + ((((size_t)b * 3 + 1) * HEADS + h) * NTOK) * HD;
    const float* vp = g_qkv + ((((size_t)b * 3 + 2) * HEADS + h) * NTOK) * HD;

    // load q/k (transposed) and v
#pragma unroll
    for (int i = 0; i < 8; ++i) {
        int e = tid + i * 256;
        int n = e >> 5, d = e & 31;
        qs[d][n] = qp[e];
        ks[d][n] = kp[e];
        vs[n][d] = vp[e];
    }
    __syncthreads();

    // row inverse norms
    if (tid < 64) {
        float s = 0.f;
#pragma unroll
        for (int d = 0; d < HD; ++d) { float v = qs[d][tid]; s = fmaf(v, v, s); }
        invq[tid] = 1.f / fmaxf(sqrtf(s), 1e-12f);
    } else if (tid < 128) {
        int r = tid - 64;
        float s = 0.f;
#pragma unroll
        for (int d = 0; d < HD; ++d) { float v = ks[d][r]; s = fmaf(v, v, s); }
        invk[r] = 1.f / fmaxf(sqrtf(s), 1e-12f);
    }
    __syncthreads();

    const float scale = expf(fminf(logit_scale[h], logf(100.f)));
    const int tx = tid & 15, ty = tid >> 4;

    // S = q @ k^T  (4x4 tile per thread)
    float acc[4][4] = {};
#pragma unroll
    for (int d = 0; d < HD; ++d) {
        float4 a = *(const float4*)&qs[d][ty * 4];
        float4 bb = *(const float4*)&ks[d][tx * 4];
        acc[0][0] = fmaf(a.x, bb.x, acc[0][0]);
        acc[0][1] = fmaf(a.x, bb.y, acc[0][1]);
        acc[0][2] = fmaf(a.x, bb.z, acc[0][2]);
        acc[0][3] = fmaf(a.x, bb.w, acc[0][3]);
        acc[1][0] = fmaf(a.y, bb.x, acc[1][0]);
        acc[1][1] = fmaf(a.y, bb.y, acc[1][1]);
        acc[1][2] = fmaf(a.y, bb.z, acc[1][2]);
        acc[1][3] = fmaf(a.y, bb.w, acc[1][3]);
        acc[2][0] = fmaf(a.z, bb.x, acc[2][0]);
        acc[2][1] = fmaf(a.z, bb.y, acc[2][1]);
        acc[2][2] = fmaf(a.z, bb.z, acc[2][2]);
        acc[2][3] = fmaf(a.z, bb.w, acc[2][3]);
        acc[3][0] = fmaf(a.w, bb.x, acc[3][0]);
        acc[3][1] = fmaf(a.w, bb.y, acc[3][1]);
        acc[3][2] = fmaf(a.w, bb.z, acc[3][2]);
        acc[3][3] = fmaf(a.w, bb.w, acc[3][3]);
    }

    const float* biasp = g_bias + (size_t)h * NTOK * NTOK;
    const float* maskp = mask + (size_t)(b & (NW - 1)) * NTOK * NTOK;
#pragma unroll
    for (int i = 0; i < 4; ++i) {
        int ii = ty * 4 + i;
#pragma unroll
        for (int j = 0; j < 4; ++j) {
            int jj = tx * 4 + j;
            S[ii][jj] = acc[i][j] * invq[ii] * invk[jj] * scale
                      + biasp[ii * NTOK + jj] + maskp[ii * NTOK + jj];
        }
    }
    __syncthreads();

    // softmax per row (thread per row)
    if (tid < 64) {
        int r = tid;
        float mx = -3.4e38f;
#pragma unroll 8
        for (int j = 0; j < NTOK; ++j) mx = fmaxf(mx, S[r][j]);
        float sum = 0.f;
#pragma unroll 8
        for (int j = 0; j < NTOK; ++j) {
            float e = __expf(S[r][j] - mx);
            S[r][j] = e;
            sum += e;
        }
        float inv = 1.f / sum;
#pragma unroll 8
        for (int j = 0; j < NTOK; ++j) S[r][j] *= inv;
    }
    __syncthreads();

    // O = S @ V : thread computes 8 outputs (n = tid/4, d = (tid%4)*8 ..)
    const int n = tid >> 2;
    const int dbase = (tid & 3) * 8;
    float o[8] = {};
#pragma unroll
    for (int m = 0; m < NTOK; ++m) {
        float p = S[n][m];
#pragma unroll
        for (int t = 0; t < 8; ++t) o[t] = fmaf(p, vs[m][dbase + t], o[t]);
    }
    float* op = g_attn + ((size_t)b * NTOK + n) * DIM + h * HD + dbase;
#pragma unroll
    for (int t = 0; t < 8; ++t) op[t] = o[t];
}

// ---------------------------------------------------------------------------
// Launch
// ---------------------------------------------------------------------------
extern "C" void kernel_launch(void* const* d_in, const int* in_sizes, int n_in,
                              void* d_out, int out_size)
{
    const float* x       = (const float*)d_in[0];
    const float* mask    = (const float*)d_in[1];
    const float* rpb     = (const float*)d_in[2];
    const int*   rpb_idx = (const int*)  d_in[3];
    const float* cpb_w1  = (const float*)d_in[4];
    const float* cpb_b1  = (const float*)d_in[5];
    const float* cpb_w2  = (const float*)d_in[6];
    const float* qkv_w   = (const float*)d_in[7];
    const float* qkv_b   = (const float*)d_in[8];
    const float* proj_w  = (const float*)d_in[9];
    const float* proj_b  = (const float*)d_in[10];
    const float* lscale  = (const float*)d_in[11];
    float* out = (float*)d_out;

    cpb_table_kernel<<<(NPOS * HEADS + 255) / 256, 256>>>(rpb, cpb_w1, cpb_b1, cpb_w2);
    bias_gather_kernel<<<(HEADS * NTOK * NTOK + 255) / 256, 256>>>(rpb_idx);

    dim3 gq(BATCH, QKVC / 64);
    qkv_gemm_kernel<<<gq, 256>>>(x, qkv_w, qkv_b);

    dim3 ga(BATCH, HEADS);
    attn_kernel<<<ga, 256>>>(lscale, mask);

    dim3 gp(BATCH, DIM / 64);
    proj_gemm_kernel<<<gp, 256>>>(proj_w, proj_b, out);
}

// round 5
// speedup vs baseline: 1.5958x; 1.5958x over previous
#include <cuda_runtime.h>
#include <cuda_bf16.h>
#include <math.h>
#include <cstdint>

// ---------------------------------------------------------------------------
// Shapes
// ---------------------------------------------------------------------------
#define BATCH   2048
#define NTOK    64
#define DIM     192
#define HEADS   6
#define HD      32
#define QKVC    576
#define NPOS    343
#define CPBH    512
#define NW      64
#define MROWS   (BATCH * NTOK)      // 131072

// ---------------------------------------------------------------------------
// Scratch (static device memory; cudaMalloc forbidden).
// NOTE: these are ONLY referenced from device code (host-side use of a
// __device__ symbol passes the shadow address -> silent corruption).
// ---------------------------------------------------------------------------
__device__ float g_qkv[(size_t)BATCH * 3 * HEADS * NTOK * HD];
__device__ __align__(16) __nv_bfloat16 g_xhi[(size_t)MROWS * DIM];
__device__ __align__(16) __nv_bfloat16 g_xlo[(size_t)MROWS * DIM];
__device__ __align__(16) __nv_bfloat16 g_ahi[(size_t)MROWS * DIM];
__device__ __align__(16) __nv_bfloat16 g_alo[(size_t)MROWS * DIM];
__device__ __align__(16) __nv_bfloat16 g_wqh[QKVC * DIM];
__device__ __align__(16) __nv_bfloat16 g_wql[QKVC * DIM];
__device__ __align__(16) __nv_bfloat16 g_wph[DIM * DIM];
__device__ __align__(16) __nv_bfloat16 g_wpl[DIM * DIM];
__device__ float g_table[NPOS * HEADS];
__device__ float g_bias[HEADS * NTOK * NTOK];

// ---------------------------------------------------------------------------
// helpers
// ---------------------------------------------------------------------------
__device__ __forceinline__ uint32_t smem_u32(const void* p) {
    uint32_t a;
    asm("{ .reg .u64 t; cvta.to.shared.u64 t, %1; cvt.u32.u64 %0, t; }" : "=r"(a) : "l"(p));
    return a;
}
__device__ __forceinline__ void ldsm_x4(uint32_t addr, uint32_t& r0, uint32_t& r1,
                                        uint32_t& r2, uint32_t& r3) {
    asm volatile("ldmatrix.sync.aligned.m8n8.x4.shared.b16 {%0,%1,%2,%3}, [%4];"
                 : "=r"(r0), "=r"(r1), "=r"(r2), "=r"(r3) : "r"(addr));
}
__device__ __forceinline__ void mma16816(float* c, uint32_t a0, uint32_t a1,
                                         uint32_t a2, uint32_t a3,
                                         uint32_t b0, uint32_t b1) {
    asm volatile("mma.sync.aligned.m16n8k16.row.col.f32.bf16.bf16.f32 "
                 "{%0,%1,%2,%3}, {%4,%5,%6,%7}, {%8,%9}, {%0,%1,%2,%3};"
                 : "+f"(c[0]), "+f"(c[1]), "+f"(c[2]), "+f"(c[3])
                 : "r"(a0), "r"(a1), "r"(a2), "r"(a3), "r"(b0), "r"(b1));
}

// ---------------------------------------------------------------------------
// split-conversion: fp32 -> bf16 hi + bf16 lo.  WHICH: 0=x, 1=qkv_w, 2=proj_w
// (outputs are internal device globals; src is a harness pointer)
// ---------------------------------------------------------------------------
template <int WHICH>
__global__ void conv_split_kernel(const float* __restrict__ src, int nElem)
{
    __nv_bfloat16* hi = (WHICH == 0) ? g_xhi : (WHICH == 1) ? g_wqh : g_wph;
    __nv_bfloat16* lo = (WHICH == 0) ? g_xlo : (WHICH == 1) ? g_wql : g_wpl;
    int t = blockIdx.x * blockDim.x + threadIdx.x;
    int base = t * 8;
    if (base >= nElem) return;
    float4 v0 = *(const float4*)(src + base);
    float4 v1 = *(const float4*)(src + base + 4);
    float v[8] = {v0.x, v0.y, v0.z, v0.w, v1.x, v1.y, v1.z, v1.w};
    __align__(16) __nv_bfloat16 h8[8], l8[8];
#pragma unroll
    for (int i = 0; i < 8; ++i) {
        __nv_bfloat16 h = __float2bfloat16(v[i]);
        h8[i] = h;
        l8[i] = __float2bfloat16(v[i] - __bfloat162float(h));
    }
    *(uint4*)(hi + base) = *(uint4*)h8;
    *(uint4*)(lo + base) = *(uint4*)l8;
}

// ---------------------------------------------------------------------------
// mma.sync split-bf16 GEMM:  C[M x NC*64] = A[M x 192] @ W^T + bias
// CTA: 128 rows x 64 cols. 8 warps (4Mx2N), warp 32x32, m16n8k16.
// smem row pitch 400B (==4 words mod 32 -> ldmatrix conflict-free).
// MODE 0: A=g_xhi/lo, W=g_wqh/l  -> scatter g_qkv.
// MODE 1: A=g_ahi/lo, W=g_wph/l  -> row-major out.
// ---------------------------------------------------------------------------
#define PITCHB 400
#define SM_AHI 0
#define SM_ALO (128 * PITCHB)
#define SM_BHI (2 * 128 * PITCHB)
#define SM_BLO (2 * 128 * PITCHB + 64 * PITCHB)
#define SM_GEMM_BYTES (2 * 128 * PITCHB + 2 * 64 * PITCHB)   // 153600

template <int MODE>
__global__ void __launch_bounds__(256, 1)
gemm_mma_kernel(const float* __restrict__ bias, float* __restrict__ out)
{
    const __nv_bfloat16* __restrict__ Ahi = (MODE == 0) ? g_xhi : g_ahi;
    const __nv_bfloat16* __restrict__ Alo = (MODE == 0) ? g_xlo : g_alo;
    const __nv_bfloat16* __restrict__ Whi = (MODE == 0) ? g_wqh : g_wph;
    const __nv_bfloat16* __restrict__ Wlo = (MODE == 0) ? g_wql : g_wpl;

    extern __shared__ __align__(16) char sm[];
    const int tid = threadIdx.x;
    const int wid = tid >> 5;
    const int lane = tid & 31;
    const int rowBase = blockIdx.x * 128;
    const int colBase = blockIdx.y * 64;

    // ---- load A tile (128 x 192 bf16 hi/lo) ----
#pragma unroll
    for (int i = tid; i < 128 * 24; i += 256) {
        int r = i / 24, c = i % 24;
        size_t g = (size_t)(rowBase + r) * DIM + c * 8;
        *(uint4*)(sm + SM_AHI + r * PITCHB + c * 16) = *(const uint4*)(Ahi + g);
        *(uint4*)(sm + SM_ALO + r * PITCHB + c * 16) = *(const uint4*)(Alo + g);
    }
    // ---- load B tile (64 x 192 bf16 hi/lo) ----
#pragma unroll
    for (int i = tid; i < 64 * 24; i += 256) {
        int r = i / 24, c = i % 24;
        size_t g = (size_t)(colBase + r) * DIM + c * 8;
        *(uint4*)(sm + SM_BHI + r * PITCHB + c * 16) = *(const uint4*)(Whi + g);
        *(uint4*)(sm + SM_BLO + r * PITCHB + c * 16) = *(const uint4*)(Wlo + g);
    }
    __syncthreads();

    const int warpM = wid >> 1;
    const int warpN = wid & 1;
    const int lrow = lane & 7;
    const int lmat = lane >> 3;

    // A x4 matrices: {m0-7@k0, m8-15@k0, m0-7@k8, m8-15@k8}
    const uint32_t aOff = (uint32_t)((warpM * 32 + lrow + (lmat & 1) * 8) * PITCHB
                                     + (lmat >> 1) * 16);
    // B x4 matrices: {n0-7@k0, n0-7@k8, n8-15@k0, n8-15@k8}
    const uint32_t bOff = (uint32_t)((warpN * 32 + lrow + (lmat >> 1) * 8) * PITCHB
                                     + (lmat & 1) * 16);

    const uint32_t smBase = smem_u32(sm);
    const uint32_t aBase[3] = { smBase + SM_AHI, smBase + SM_AHI, smBase + SM_ALO };
    const uint32_t bBase[3] = { smBase + SM_BHI, smBase + SM_BLO, smBase + SM_BHI };

    float c[2][4][4] = {};

#pragma unroll
    for (int p = 0; p < 3; ++p) {
        const uint32_t aT = aBase[p] + aOff;
        const uint32_t bT = bBase[p] + bOff;
#pragma unroll
        for (int k = 0; k < 12; ++k) {
            uint32_t a[2][4], bfr[2][4];
            ldsm_x4(aT + k * 32,               a[0][0], a[0][1], a[0][2], a[0][3]);
            ldsm_x4(aT + 16 * PITCHB + k * 32, a[1][0], a[1][1], a[1][2], a[1][3]);
            ldsm_x4(bT + k * 32,               bfr[0][0], bfr[0][1], bfr[0][2], bfr[0][3]);
            ldsm_x4(bT + 16 * PITCHB + k * 32, bfr[1][0], bfr[1][1], bfr[1][2], bfr[1][3]);
#pragma unroll
            for (int mi = 0; mi < 2; ++mi) {
#pragma unroll
                for (int ni = 0; ni < 4; ++ni) {
                    mma16816(c[mi][ni], a[mi][0], a[mi][1], a[mi][2], a[mi][3],
                             bfr[ni >> 1][(ni & 1) * 2], bfr[ni >> 1][(ni & 1) * 2 + 1]);
                }
            }
        }
    }

    // ---- epilogue ----
    const int g = lane >> 2, tig = lane & 3;
#pragma unroll
    for (int mi = 0; mi < 2; ++mi) {
#pragma unroll
        for (int ni = 0; ni < 4; ++ni) {
            int row0 = rowBase + warpM * 32 + mi * 16 + g;
            int col = colBase + warpN * 32 + ni * 8 + tig * 2;
            float b0 = bias[col], b1 = bias[col + 1];
#pragma unroll
            for (int rr = 0; rr < 2; ++rr) {
                int row = row0 + rr * 8;
                float2 val = make_float2(c[mi][ni][rr * 2] + b0, c[mi][ni][rr * 2 + 1] + b1);
                if (MODE == 0) {
                    int b = row >> 6, n = row & 63;
                    int which = col / DIM;
                    int rem = col - which * DIM;
                    int h = rem >> 5, d = rem & 31;
                    size_t idx = ((((size_t)b * 3 + which) * HEADS + h) * NTOK + n) * HD + d;
                    *(float2*)(g_qkv + idx) = val;
                } else {
                    *(float2*)(out + (size_t)row * DIM + col) = val;
                }
            }
        }
    }
}

// ---------------------------------------------------------------------------
// CPB MLP + bias gather
// ---------------------------------------------------------------------------
__global__ void cpb_table_kernel(const float* __restrict__ rpb,
                                 const float* __restrict__ w1,
                                 const float* __restrict__ b1,
                                 const float* __restrict__ w2)
{
    int idx = blockIdx.x * blockDim.x + threadIdx.x;
    if (idx >= NPOS * HEADS) return;
    int p = idx / HEADS, h = idx % HEADS;
    float r0 = rpb[p * 3 + 0], r1 = rpb[p * 3 + 1], r2 = rpb[p * 3 + 2];
    float acc = 0.f;
#pragma unroll 4
    for (int j = 0; j < CPBH; ++j) {
        float hv = fmaf(w1[j * 3 + 0], r0, fmaf(w1[j * 3 + 1], r1, fmaf(w1[j * 3 + 2], r2, b1[j])));
        acc = fmaf(fmaxf(hv, 0.f), w2[h * CPBH + j], acc);
    }
    g_table[p * HEADS + h] = acc;
}

__global__ void bias_gather_kernel(const int* __restrict__ rpb_idx)
{
    int idx = blockIdx.x * blockDim.x + threadIdx.x;
    if (idx >= HEADS * NTOK * NTOK) return;
    int h = idx / (NTOK * NTOK);
    int ij = idx % (NTOK * NTOK);
    float t = g_table[rpb_idx[ij] * HEADS + h];
    g_bias[idx] = 16.f / (1.f + expf(-t));
}

// ---------------------------------------------------------------------------
// attention: per-(window, head); output written as bf16 hi/lo for proj GEMM
// ---------------------------------------------------------------------------
__global__ void attn_kernel(const float* __restrict__ logit_scale,
                            const float* __restrict__ mask)
{
    __shared__ __align__(16) float qs[HD][68];
    __shared__ __align__(16) float ks[HD][68];
    __shared__ float vs[NTOK][33];
    __shared__ float S[NTOK][65];
    __shared__ float invq[NTOK], invk[NTOK];

    const int b = blockIdx.x;
    const int h = blockIdx.y;
    const int tid = threadIdx.x;

    const float* qp = g_qkv + ((((size_t)b * 3 + 0) * HEADS + h) * NTOK) * HD;
    const float* kp = g_qkv + ((((size_t)b * 3 + 1) * HEADS + h) * NTOK) * HD;
    const float* vp = g_qkv + ((((size_t)b * 3 + 2) * HEADS + h) * NTOK) * HD;

#pragma unroll
    for (int i = 0; i < 8; ++i) {
        int e = tid + i * 256;
        int n = e >> 5, d = e & 31;
        qs[d][n] = qp[e];
        ks[d][n] = kp[e];
        vs[n][d] = vp[e];
    }
    __syncthreads();

    if (tid < 64) {
        float s = 0.f;
#pragma unroll
        for (int d = 0; d < HD; ++d) { float v = qs[d][tid]; s = fmaf(v, v, s); }
        invq[tid] = 1.f / fmaxf(sqrtf(s), 1e-12f);
    } else if (tid < 128) {
        int r = tid - 64;
        float s = 0.f;
#pragma unroll
        for (int d = 0; d < HD; ++d) { float v = ks[d][r]; s = fmaf(v, v, s); }
        invk[r] = 1.f / fmaxf(sqrtf(s), 1e-12f);
    }
    __syncthreads();

    const float scale = expf(fminf(logit_scale[h], logf(100.f)));
    const int tx = tid & 15, ty = tid >> 4;

    float acc[4][4] = {};
#pragma unroll
    for (int d = 0; d < HD; ++d) {
        float4 a = *(const float4*)&qs[d][ty * 4];
        float4 bb = *(const float4*)&ks[d][tx * 4];
        acc[0][0] = fmaf(a.x, bb.x, acc[0][0]); acc[0][1] = fmaf(a.x, bb.y, acc[0][1]);
        acc[0][2] = fmaf(a.x, bb.z, acc[0][2]); acc[0][3] = fmaf(a.x, bb.w, acc[0][3]);
        acc[1][0] = fmaf(a.y, bb.x, acc[1][0]); acc[1][1] = fmaf(a.y, bb.y, acc[1][1]);
        acc[1][2] = fmaf(a.y, bb.z, acc[1][2]); acc[1][3] = fmaf(a.y, bb.w, acc[1][3]);
        acc[2][0] = fmaf(a.z, bb.x, acc[2][0]); acc[2][1] = fmaf(a.z, bb.y, acc[2][1]);
        acc[2][2] = fmaf(a.z, bb.z, acc[2][2]); acc[2][3] = fmaf(a.z, bb.w, acc[2][3]);
        acc[3][0] = fmaf(a.w, bb.x, acc[3][0]); acc[3][1] = fmaf(a.w, bb.y, acc[3][1]);
        acc[3][2] = fmaf(a.w, bb.z, acc[3][2]); acc[3][3] = fmaf(a.w, bb.w, acc[3][3]);
    }

    const float* biasp = g_bias + (size_t)h * NTOK * NTOK;
    const float* maskp = mask + (size_t)(b & (NW - 1)) * NTOK * NTOK;
#pragma unroll
    for (int i = 0; i < 4; ++i) {
        int ii = ty * 4 + i;
#pragma unroll
        for (int j = 0; j < 4; ++j) {
            int jj = tx * 4 + j;
            S[ii][jj] = acc[i][j] * invq[ii] * invk[jj] * scale
                      + biasp[ii * NTOK + jj] + maskp[ii * NTOK + jj];
        }
    }
    __syncthreads();

    if (tid < 64) {
        int r = tid;
        float mx = -3.4e38f;
#pragma unroll 8
        for (int j = 0; j < NTOK; ++j) mx = fmaxf(mx, S[r][j]);
        float sum = 0.f;
#pragma unroll 8
        for (int j = 0; j < NTOK; ++j) { float e = __expf(S[r][j] - mx); S[r][j] = e; sum += e; }
        float inv = 1.f / sum;
#pragma unroll 8
        for (int j = 0; j < NTOK; ++j) S[r][j] *= inv;
    }
    __syncthreads();

    const int n = tid >> 2;
    const int dbase = (tid & 3) * 8;
    float o[8] = {};
#pragma unroll
    for (int m = 0; m < NTOK; ++m) {
        float p = S[n][m];
#pragma unroll
        for (int t = 0; t < 8; ++t) o[t] = fmaf(p, vs[m][dbase + t], o[t]);
    }
    size_t oidx = ((size_t)b * NTOK + n) * DIM + h * HD + dbase;
    __align__(16) __nv_bfloat16 h8[8], l8[8];
#pragma unroll
    for (int t = 0; t < 8; ++t) {
        __nv_bfloat16 hv = __float2bfloat16(o[t]);
        h8[t] = hv;
        l8[t] = __float2bfloat16(o[t] - __bfloat162float(hv));
    }
    *(uint4*)(g_ahi + oidx) = *(uint4*)h8;
    *(uint4*)(g_alo + oidx) = *(uint4*)l8;
}

// ---------------------------------------------------------------------------
// Launch
// ---------------------------------------------------------------------------
extern "C" void kernel_launch(void* const* d_in, const int* in_sizes, int n_in,
                              void* d_out, int out_size)
{
    const float* x       = (const float*)d_in[0];
    const float* mask    = (const float*)d_in[1];
    const float* rpb     = (const float*)d_in[2];
    const int*   rpb_idx = (const int*)  d_in[3];
    const float* cpb_w1  = (const float*)d_in[4];
    const float* cpb_b1  = (const float*)d_in[5];
    const float* cpb_w2  = (const float*)d_in[6];
    const float* qkv_w   = (const float*)d_in[7];
    const float* qkv_b   = (const float*)d_in[8];
    const float* proj_w  = (const float*)d_in[9];
    const float* proj_b  = (const float*)d_in[10];
    const float* lscale  = (const float*)d_in[11];
    float* out = (float*)d_out;

    cudaFuncSetAttribute(gemm_mma_kernel<0>, cudaFuncAttributeMaxDynamicSharedMemorySize, SM_GEMM_BYTES);
    cudaFuncSetAttribute(gemm_mma_kernel<1>, cudaFuncAttributeMaxDynamicSharedMemorySize, SM_GEMM_BYTES);

    conv_split_kernel<0><<<(MROWS * DIM / 8 + 255) / 256, 256>>>(x, MROWS * DIM);
    conv_split_kernel<1><<<(QKVC * DIM / 8 + 255) / 256, 256>>>(qkv_w, QKVC * DIM);
    conv_split_kernel<2><<<(DIM * DIM / 8 + 255) / 256, 256>>>(proj_w, DIM * DIM);

    cpb_table_kernel<<<(NPOS * HEADS + 255) / 256, 256>>>(rpb, cpb_w1, cpb_b1, cpb_w2);
    bias_gather_kernel<<<(HEADS * NTOK * NTOK + 255) / 256, 256>>>(rpb_idx);

    dim3 gq(MROWS / 128, QKVC / 64);
    gemm_mma_kernel<0><<<gq, 256, SM_GEMM_BYTES>>>(qkv_b, nullptr);

    dim3 ga(BATCH, HEADS);
    attn_kernel<<<ga, 256>>>(lscale, mask);

    dim3 gp(MROWS / 128, DIM / 64);
    gemm_mma_kernel<1><<<gp, 256, SM_GEMM_BYTES>>>(proj_b, out);
}

// round 6
// speedup vs baseline: 2.1504x; 1.3475x over previous
#include <cuda_runtime.h>
#include <cuda_bf16.h>
#include <math.h>
#include <cstdint>

// ---------------------------------------------------------------------------
// Shapes
// ---------------------------------------------------------------------------
#define BATCH   2048
#define NTOK    64
#define DIM     192
#define HEADS   6
#define HD      32
#define QKVC    576
#define NPOS    343
#define CPBH    512
#define NW      64
#define MROWS   (BATCH * NTOK)      // 131072

// ---------------------------------------------------------------------------
// Scratch (device-code-only references!)
// ---------------------------------------------------------------------------
__device__ float g_qkv[(size_t)BATCH * 3 * HEADS * NTOK * HD];
__device__ float g_attn[(size_t)MROWS * DIM];
__device__ __align__(16) __nv_bfloat16 g_wqh[QKVC * DIM];
__device__ __align__(16) __nv_bfloat16 g_wql[QKVC * DIM];
__device__ __align__(16) __nv_bfloat16 g_wph[DIM * DIM];
__device__ __align__(16) __nv_bfloat16 g_wpl[DIM * DIM];
__device__ float g_table[NPOS * HEADS];
__device__ float g_bias[HEADS * NTOK * NTOK];
__device__ float g_bm[(size_t)NW * HEADS * NTOK * NTOK];   // bias+mask combined

// ---------------------------------------------------------------------------
// helpers
// ---------------------------------------------------------------------------
__device__ __forceinline__ uint32_t smem_u32(const void* p) {
    uint32_t a;
    asm("{ .reg .u64 t; cvta.to.shared.u64 t, %1; cvt.u32.u64 %0, t; }" : "=r"(a) : "l"(p));
    return a;
}
__device__ __forceinline__ void ldsm_x4(uint32_t addr, uint32_t& r0, uint32_t& r1,
                                        uint32_t& r2, uint32_t& r3) {
    asm volatile("ldmatrix.sync.aligned.m8n8.x4.shared.b16 {%0,%1,%2,%3}, [%4];"
                 : "=r"(r0), "=r"(r1), "=r"(r2), "=r"(r3) : "r"(addr));
}
__device__ __forceinline__ void mma16816(float* c, uint32_t a0, uint32_t a1,
                                         uint32_t a2, uint32_t a3,
                                         uint32_t b0, uint32_t b1) {
    asm volatile("mma.sync.aligned.m16n8k16.row.col.f32.bf16.bf16.f32 "
                 "{%0,%1,%2,%3}, {%4,%5,%6,%7}, {%8,%9}, {%0,%1,%2,%3};"
                 : "+f"(c[0]), "+f"(c[1]), "+f"(c[2]), "+f"(c[3])
                 : "r"(a0), "r"(a1), "r"(a2), "r"(a3), "r"(b0), "r"(b1));
}

// ---------------------------------------------------------------------------
// weight split-conversion: WHICH 0 = qkv_w, 1 = proj_w
// ---------------------------------------------------------------------------
template <int WHICH>
__global__ void conv_w_kernel(const float* __restrict__ src, int nElem)
{
    __nv_bfloat16* hi = (WHICH == 0) ? g_wqh : g_wph;
    __nv_bfloat16* lo = (WHICH == 0) ? g_wql : g_wpl;
    int base = (blockIdx.x * blockDim.x + threadIdx.x) * 8;
    if (base >= nElem) return;
    float4 v0 = *(const float4*)(src + base);
    float4 v1 = *(const float4*)(src + base + 4);
    float v[8] = {v0.x, v0.y, v0.z, v0.w, v1.x, v1.y, v1.z, v1.w};
    __align__(16) __nv_bfloat16 h8[8], l8[8];
#pragma unroll
    for (int i = 0; i < 8; ++i) {
        __nv_bfloat16 h = __float2bfloat16(v[i]);
        h8[i] = h;
        l8[i] = __float2bfloat16(v[i] - __bfloat162float(h));
    }
    *(uint4*)(hi + base) = *(uint4*)h8;
    *(uint4*)(lo + base) = *(uint4*)l8;
}

// ---------------------------------------------------------------------------
// GEMM: A-resident, loop over N chunks. CTA = 128 rows; per chunk 64 cols.
// A loaded fp32 + split in-kernel. 8 warps (4Mx2N), m16n8k16, 3-pass split.
// MODE 0: A=x (param) NC=9 -> scatter g_qkv.   MODE 1: A=g_attn NC=3 -> out.
// ---------------------------------------------------------------------------
#define PITCHB 400
#define SM_AHI 0
#define SM_ALO (128 * PITCHB)
#define SM_BHI (2 * 128 * PITCHB)
#define SM_BLO (2 * 128 * PITCHB + 64 * PITCHB)
#define SM_GEMM_BYTES (2 * 128 * PITCHB + 2 * 64 * PITCHB)   // 153600

template <int MODE>
__global__ void __launch_bounds__(256, 1)
gemm_mma_kernel(const float* __restrict__ Ain,
                const float* __restrict__ bias, float* __restrict__ out)
{
    constexpr int NC = (MODE == 0) ? 9 : 3;
    const float* __restrict__ A = (MODE == 0) ? Ain : g_attn;
    const __nv_bfloat16* __restrict__ Whi = (MODE == 0) ? g_wqh : g_wph;
    const __nv_bfloat16* __restrict__ Wlo = (MODE == 0) ? g_wql : g_wpl;

    extern __shared__ __align__(16) char sm[];
    const int tid = threadIdx.x;
    const int wid = tid >> 5;
    const int lane = tid & 31;
    const int rowBase = blockIdx.x * 128;

    // ---- load A fp32 -> split to smem hi/lo (128 x 192) ----
#pragma unroll
    for (int i = tid; i < 128 * 48; i += 256) {
        int r = i / 48, c4 = i % 48;
        float4 v = *(const float4*)(A + (size_t)(rowBase + r) * DIM + c4 * 4);
        float vv[4] = {v.x, v.y, v.z, v.w};
        __align__(8) __nv_bfloat16 h4[4], l4[4];
#pragma unroll
        for (int q = 0; q < 4; ++q) {
            __nv_bfloat16 h = __float2bfloat16(vv[q]);
            h4[q] = h;
            l4[q] = __float2bfloat16(vv[q] - __bfloat162float(h));
        }
        *(uint2*)(sm + SM_AHI + r * PITCHB + c4 * 8) = *(uint2*)h4;
        *(uint2*)(sm + SM_ALO + r * PITCHB + c4 * 8) = *(uint2*)l4;
    }

    const int warpM = wid >> 1;
    const int warpN = wid & 1;
    const int lrow = lane & 7;
    const int lmat = lane >> 3;

    const uint32_t aOff = (uint32_t)((warpM * 32 + lrow + (lmat & 1) * 8) * PITCHB
                                     + (lmat >> 1) * 16);
    const uint32_t bOff = (uint32_t)((warpN * 32 + lrow + (lmat >> 1) * 8) * PITCHB
                                     + (lmat & 1) * 16);

    const uint32_t smBase = smem_u32(sm);
    const uint32_t aBase[3] = { smBase + SM_AHI, smBase + SM_AHI, smBase + SM_ALO };
    const uint32_t bBase[3] = { smBase + SM_BHI, smBase + SM_BLO, smBase + SM_BHI };
    const int g = lane >> 2, tig = lane & 3;

    for (int cc = 0; cc < NC; ++cc) {
        const int colBase = cc * 64;
        // ---- load B chunk (64 x 192 hi/lo pre-split) ----
#pragma unroll
        for (int i = tid; i < 64 * 24; i += 256) {
            int r = i / 24, c = i % 24;
            size_t gg = (size_t)(colBase + r) * DIM + c * 8;
            *(uint4*)(sm + SM_BHI + r * PITCHB + c * 16) = *(const uint4*)(Whi + gg);
            *(uint4*)(sm + SM_BLO + r * PITCHB + c * 16) = *(const uint4*)(Wlo + gg);
        }
        __syncthreads();

        float c[2][4][4] = {};
#pragma unroll
        for (int p = 0; p < 3; ++p) {
            const uint32_t aT = aBase[p] + aOff;
            const uint32_t bT = bBase[p] + bOff;
#pragma unroll
            for (int k = 0; k < 12; ++k) {
                uint32_t a[2][4], bfr[2][4];
                ldsm_x4(aT + k * 32,               a[0][0], a[0][1], a[0][2], a[0][3]);
                ldsm_x4(aT + 16 * PITCHB + k * 32, a[1][0], a[1][1], a[1][2], a[1][3]);
                ldsm_x4(bT + k * 32,               bfr[0][0], bfr[0][1], bfr[0][2], bfr[0][3]);
                ldsm_x4(bT + 16 * PITCHB + k * 32, bfr[1][0], bfr[1][1], bfr[1][2], bfr[1][3]);
#pragma unroll
                for (int mi = 0; mi < 2; ++mi)
#pragma unroll
                    for (int ni = 0; ni < 4; ++ni)
                        mma16816(c[mi][ni], a[mi][0], a[mi][1], a[mi][2], a[mi][3],
                                 bfr[ni >> 1][(ni & 1) * 2], bfr[ni >> 1][(ni & 1) * 2 + 1]);
            }
        }

        // ---- epilogue ----
#pragma unroll
        for (int mi = 0; mi < 2; ++mi) {
#pragma unroll
            for (int ni = 0; ni < 4; ++ni) {
                int row0 = rowBase + warpM * 32 + mi * 16 + g;
                int col = colBase + warpN * 32 + ni * 8 + tig * 2;
                float b0 = bias[col], b1 = bias[col + 1];
#pragma unroll
                for (int rr = 0; rr < 2; ++rr) {
                    int row = row0 + rr * 8;
                    float2 val = make_float2(c[mi][ni][rr * 2] + b0, c[mi][ni][rr * 2 + 1] + b1);
                    if (MODE == 0) {
                        int b = row >> 6, n = row & 63;
                        int which = col / DIM;
                        int rem = col - which * DIM;
                        int h = rem >> 5, d = rem & 31;
                        size_t idx = ((((size_t)b * 3 + which) * HEADS + h) * NTOK + n) * HD + d;
                        *(float2*)(g_qkv + idx) = val;
                    } else {
                        *(float2*)(out + (size_t)row * DIM + col) = val;
                    }
                }
            }
        }
        __syncthreads();   // B consumed before refill
    }
}

// ---------------------------------------------------------------------------
// CPB MLP (block per position, shuffle-reduced)
// ---------------------------------------------------------------------------
__global__ void cpb_table_kernel(const float* __restrict__ rpb,
                                 const float* __restrict__ w1,
                                 const float* __restrict__ b1,
                                 const float* __restrict__ w2)
{
    __shared__ float red[4][HEADS];
    const int p = blockIdx.x;
    const int tid = threadIdx.x;
    float r0 = rpb[p * 3 + 0], r1 = rpb[p * 3 + 1], r2 = rpb[p * 3 + 2];
    float acc[HEADS] = {};
    for (int j = tid; j < CPBH; j += 128) {
        float hv = fmaf(w1[j * 3 + 0], r0, fmaf(w1[j * 3 + 1], r1, fmaf(w1[j * 3 + 2], r2, b1[j])));
        hv = fmaxf(hv, 0.f);
#pragma unroll
        for (int h = 0; h < HEADS; ++h) acc[h] = fmaf(hv, w2[h * CPBH + j], acc[h]);
    }
#pragma unroll
    for (int h = 0; h < HEADS; ++h)
#pragma unroll
        for (int s = 16; s; s >>= 1) acc[h] += __shfl_xor_sync(~0u, acc[h], s);
    if ((tid & 31) == 0) {
#pragma unroll
        for (int h = 0; h < HEADS; ++h) red[tid >> 5][h] = acc[h];
    }
    __syncthreads();
    if (tid < HEADS)
        g_table[p * HEADS + tid] = red[0][tid] + red[1][tid] + red[2][tid] + red[3][tid];
}

__global__ void bias_gather_kernel(const int* __restrict__ rpb_idx)
{
    int idx = blockIdx.x * blockDim.x + threadIdx.x;
    if (idx >= HEADS * NTOK * NTOK) return;
    int h = idx / (NTOK * NTOK);
    int ij = idx % (NTOK * NTOK);
    float t = g_table[rpb_idx[ij] * HEADS + h];
    g_bias[idx] = 16.f / (1.f + expf(-t));
}

// combined bias+mask table: g_bm[w][h][ij]
__global__ void bm_kernel(const float* __restrict__ mask)
{
    int w = blockIdx.x, h = blockIdx.y;
    const float* mp = mask + (size_t)w * NTOK * NTOK;
    const float* bp = g_bias + (size_t)h * NTOK * NTOK;
    float* o = g_bm + ((size_t)(w * HEADS + h)) * NTOK * NTOK;
    for (int ij = threadIdx.x; ij < NTOK * NTOK; ij += 256)
        o[ij] = bp[ij] + mp[ij];
}

// ---------------------------------------------------------------------------
// attention: per-(window, head)
// ---------------------------------------------------------------------------
__global__ void attn_kernel(const float* __restrict__ logit_scale)
{
    __shared__ __align__(16) float qs[HD][68];
    __shared__ __align__(16) float ks[HD][68];
    __shared__ __align__(16) float vs[NTOK][36];
    __shared__ float S[NTOK][65];
    __shared__ float invq[NTOK], invk[NTOK];

    const int b = blockIdx.x;
    const int h = blockIdx.y;
    const int tid = threadIdx.x;

    const float* qp = g_qkv + ((((size_t)b * 3 + 0) * HEADS + h) * NTOK) * HD;
    const float* kp = g_qkv + ((((size_t)b * 3 + 1) * HEADS + h) * NTOK) * HD;
    const float* vp = g_qkv + ((((size_t)b * 3 + 2) * HEADS + h) * NTOK) * HD;

#pragma unroll
    for (int i = 0; i < 8; ++i) {
        int e = tid + i * 256;
        int n = e >> 5, d = e & 31;
        qs[d][n] = qp[e];
        ks[d][n] = kp[e];
        vs[n][d] = vp[e];
    }
    __syncthreads();

    if (tid < 64) {
        float s = 0.f;
#pragma unroll
        for (int d = 0; d < HD; ++d) { float v = qs[d][tid]; s = fmaf(v, v, s); }
        invq[tid] = 1.f / fmaxf(sqrtf(s), 1e-12f);
    } else if (tid < 128) {
        int r = tid - 64;
        float s = 0.f;
#pragma unroll
        for (int d = 0; d < HD; ++d) { float v = ks[d][r]; s = fmaf(v, v, s); }
        invk[r] = 1.f / fmaxf(sqrtf(s), 1e-12f);
    }
    __syncthreads();

    const float scale = expf(fminf(logit_scale[h], logf(100.f)));
    const int tx = tid & 15, ty = tid >> 4;

    float acc[4][4] = {};
#pragma unroll
    for (int d = 0; d < HD; ++d) {
        float4 a = *(const float4*)&qs[d][ty * 4];
        float4 bb = *(const float4*)&ks[d][tx * 4];
        acc[0][0] = fmaf(a.x, bb.x, acc[0][0]); acc[0][1] = fmaf(a.x, bb.y, acc[0][1]);
        acc[0][2] = fmaf(a.x, bb.z, acc[0][2]); acc[0][3] = fmaf(a.x, bb.w, acc[0][3]);
        acc[1][0] = fmaf(a.y, bb.x, acc[1][0]); acc[1][1] = fmaf(a.y, bb.y, acc[1][1]);
        acc[1][2] = fmaf(a.y, bb.z, acc[1][2]); acc[1][3] = fmaf(a.y, bb.w, acc[1][3]);
        acc[2][0] = fmaf(a.z, bb.x, acc[2][0]); acc[2][1] = fmaf(a.z, bb.y, acc[2][1]);
        acc[2][2] = fmaf(a.z, bb.z, acc[2][2]); acc[2][3] = fmaf(a.z, bb.w, acc[2][3]);
        acc[3][0] = fmaf(a.w, bb.x, acc[3][0]); acc[3][1] = fmaf(a.w, bb.y, acc[3][1]);
        acc[3][2] = fmaf(a.w, bb.z, acc[3][2]); acc[3][3] = fmaf(a.w, bb.w, acc[3][3]);
    }

    const float* bmp = g_bm + ((size_t)((b & (NW - 1)) * HEADS + h)) * NTOK * NTOK;
#pragma unroll
    for (int i = 0; i < 4; ++i) {
        int ii = ty * 4 + i;
#pragma unroll
        for (int j = 0; j < 4; ++j) {
            int jj = tx * 4 + j;
            S[ii][jj] = acc[i][j] * invq[ii] * invk[jj] * scale + bmp[ii * NTOK + jj];
        }
    }
    __syncthreads();

    if (tid < 64) {
        int r = tid;
        float mx = -3.4e38f;
#pragma unroll 8
        for (int j = 0; j < NTOK; ++j) mx = fmaxf(mx, S[r][j]);
        float sum = 0.f;
#pragma unroll 8
        for (int j = 0; j < NTOK; ++j) { float e = __expf(S[r][j] - mx); S[r][j] = e; sum += e; }
        float inv = 1.f / sum;
#pragma unroll 8
        for (int j = 0; j < NTOK; ++j) S[r][j] *= inv;
    }
    __syncthreads();

    // PV: thread computes rows {2tn, 2tn+1} x cols [4td, 4td+4)
    const int tn = tid >> 3;
    const int td = tid & 7;
    float o0[4] = {}, o1[4] = {};
#pragma unroll 8
    for (int m = 0; m < NTOK; ++m) {
        float4 v4 = *(const float4*)&vs[m][td * 4];
        float p0 = S[2 * tn][m], p1 = S[2 * tn + 1][m];
        o0[0] = fmaf(p0, v4.x, o0[0]); o0[1] = fmaf(p0, v4.y, o0[1]);
        o0[2] = fmaf(p0, v4.z, o0[2]); o0[3] = fmaf(p0, v4.w, o0[3]);
        o1[0] = fmaf(p1, v4.x, o1[0]); o1[1] = fmaf(p1, v4.y, o1[1]);
        o1[2] = fmaf(p1, v4.z, o1[2]); o1[3] = fmaf(p1, v4.w, o1[3]);
    }
    float* op = g_attn + ((size_t)b * NTOK + 2 * tn) * DIM + h * HD + td * 4;
    *(float4*)op = make_float4(o0[0], o0[1], o0[2], o0[3]);
    *(float4*)(op + DIM) = make_float4(o1[0], o1[1], o1[2], o1[3]);
}

// ---------------------------------------------------------------------------
// Launch
// ---------------------------------------------------------------------------
extern "C" void kernel_launch(void* const* d_in, const int* in_sizes, int n_in,
                              void* d_out, int out_size)
{
    const float* x       = (const float*)d_in[0];
    const float* mask    = (const float*)d_in[1];
    const float* rpb     = (const float*)d_in[2];
    const int*   rpb_idx = (const int*)  d_in[3];
    const float* cpb_w1  = (const float*)d_in[4];
    const float* cpb_b1  = (const float*)d_in[5];
    const float* cpb_w2  = (const float*)d_in[6];
    const float* qkv_w   = (const float*)d_in[7];
    const float* qkv_b   = (const float*)d_in[8];
    const float* proj_w  = (const float*)d_in[9];
    const float* proj_b  = (const float*)d_in[10];
    const float* lscale  = (const float*)d_in[11];
    float* out = (float*)d_out;

    cudaFuncSetAttribute(gemm_mma_kernel<0>, cudaFuncAttributeMaxDynamicSharedMemorySize, SM_GEMM_BYTES);
    cudaFuncSetAttribute(gemm_mma_kernel<1>, cudaFuncAttributeMaxDynamicSharedMemorySize, SM_GEMM_BYTES);

    conv_w_kernel<0><<<(QKVC * DIM / 8 + 255) / 256, 256>>>(qkv_w, QKVC * DIM);
    conv_w_kernel<1><<<(DIM * DIM / 8 + 255) / 256, 256>>>(proj_w, DIM * DIM);

    cpb_table_kernel<<<NPOS, 128>>>(rpb, cpb_w1, cpb_b1, cpb_w2);
    bias_gather_kernel<<<(HEADS * NTOK * NTOK + 255) / 256, 256>>>(rpb_idx);
    bm_kernel<<<dim3(NW, HEADS), 256>>>(mask);

    gemm_mma_kernel<0><<<MROWS / 128, 256, SM_GEMM_BYTES>>>(x, qkv_b, nullptr);

    dim3 ga(BATCH, HEADS);
    attn_kernel<<<ga, 256>>>(lscale);

    gemm_mma_kernel<1><<<MROWS / 128, 256, SM_GEMM_BYTES>>>(nullptr, proj_b, out);
}

// round 7
// speedup vs baseline: 2.7753x; 1.2906x over previous
#include <cuda_runtime.h>
#include <cuda_bf16.h>
#include <math.h>
#include <cstdint>

// ---------------------------------------------------------------------------
// Shapes
// ---------------------------------------------------------------------------
#define BATCH   2048
#define NTOK    64
#define DIM     192
#define HEADS   6
#define HD      32
#define QKVC    576
#define NPOS    343
#define CPBH    512
#define NW      64
#define MROWS   (BATCH * NTOK)      // 131072

// ---------------------------------------------------------------------------
// Scratch (device-code-only references!)
// ---------------------------------------------------------------------------
__device__ float g_qkv[(size_t)BATCH * 3 * HEADS * NTOK * HD];
__device__ float g_attn[(size_t)MROWS * DIM];
__device__ __align__(16) __nv_bfloat16 g_wqh[QKVC * DIM];
__device__ __align__(16) __nv_bfloat16 g_wql[QKVC * DIM];
__device__ __align__(16) __nv_bfloat16 g_wph[DIM * DIM];
__device__ __align__(16) __nv_bfloat16 g_wpl[DIM * DIM];
__device__ float g_table[NPOS * HEADS];
__device__ float g_bias[HEADS * NTOK * NTOK];
__device__ float g_bm[(size_t)NW * HEADS * NTOK * NTOK];

// ---------------------------------------------------------------------------
// helpers
// ---------------------------------------------------------------------------
__device__ __forceinline__ uint32_t smem_u32(const void* p) {
    uint32_t a;
    asm("{ .reg .u64 t; cvta.to.shared.u64 t, %1; cvt.u32.u64 %0, t; }" : "=r"(a) : "l"(p));
    return a;
}
__device__ __forceinline__ void ldsm_x4(uint32_t addr, uint32_t& r0, uint32_t& r1,
                                        uint32_t& r2, uint32_t& r3) {
    asm volatile("ldmatrix.sync.aligned.m8n8.x4.shared.b16 {%0,%1,%2,%3}, [%4];"
                 : "=r"(r0), "=r"(r1), "=r"(r2), "=r"(r3) : "r"(addr));
}
__device__ __forceinline__ void mma16816(float* c, uint32_t a0, uint32_t a1,
                                         uint32_t a2, uint32_t a3,
                                         uint32_t b0, uint32_t b1) {
    asm volatile("mma.sync.aligned.m16n8k16.row.col.f32.bf16.bf16.f32 "
                 "{%0,%1,%2,%3}, {%4,%5,%6,%7}, {%8,%9}, {%0,%1,%2,%3};"
                 : "+f"(c[0]), "+f"(c[1]), "+f"(c[2]), "+f"(c[3])
                 : "r"(a0), "r"(a1), "r"(a2), "r"(a3), "r"(b0), "r"(b1));
}
__device__ __forceinline__ uint32_t pk_bf16(float x0, float x1) {
    __nv_bfloat162 t = __floats2bfloat162_rn(x0, x1);
    return *(uint32_t*)&t;
}

// ---------------------------------------------------------------------------
// weight split-conversion: WHICH 0 = qkv_w, 1 = proj_w
// ---------------------------------------------------------------------------
template <int WHICH>
__global__ void conv_w_kernel(const float* __restrict__ src, int nElem)
{
    __nv_bfloat16* hi = (WHICH == 0) ? g_wqh : g_wph;
    __nv_bfloat16* lo = (WHICH == 0) ? g_wql : g_wpl;
    int base = (blockIdx.x * blockDim.x + threadIdx.x) * 8;
    if (base >= nElem) return;
    float4 v0 = *(const float4*)(src + base);
    float4 v1 = *(const float4*)(src + base + 4);
    float v[8] = {v0.x, v0.y, v0.z, v0.w, v1.x, v1.y, v1.z, v1.w};
    __align__(16) __nv_bfloat16 h8[8], l8[8];
#pragma unroll
    for (int i = 0; i < 8; ++i) {
        __nv_bfloat16 h = __float2bfloat16(v[i]);
        h8[i] = h;
        l8[i] = __float2bfloat16(v[i] - __bfloat162float(h));
    }
    *(uint4*)(hi + base) = *(uint4*)h8;
    *(uint4*)(lo + base) = *(uint4*)l8;
}

// ---------------------------------------------------------------------------
// GEMM (unchanged from round 6): A-resident, N-chunk loop, 3-pass split bf16
// ---------------------------------------------------------------------------
#define PITCHB 400
#define SM_AHI 0
#define SM_ALO (128 * PITCHB)
#define SM_BHI (2 * 128 * PITCHB)
#define SM_BLO (2 * 128 * PITCHB + 64 * PITCHB)
#define SM_GEMM_BYTES (2 * 128 * PITCHB + 2 * 64 * PITCHB)   // 153600

template <int MODE>
__global__ void __launch_bounds__(256, 1)
gemm_mma_kernel(const float* __restrict__ Ain,
                const float* __restrict__ bias, float* __restrict__ out)
{
    constexpr int NC = (MODE == 0) ? 9 : 3;
    const float* __restrict__ A = (MODE == 0) ? Ain : g_attn;
    const __nv_bfloat16* __restrict__ Whi = (MODE == 0) ? g_wqh : g_wph;
    const __nv_bfloat16* __restrict__ Wlo = (MODE == 0) ? g_wql : g_wpl;

    extern __shared__ __align__(16) char sm[];
    const int tid = threadIdx.x;
    const int wid = tid >> 5;
    const int lane = tid & 31;
    const int rowBase = blockIdx.x * 128;

#pragma unroll
    for (int i = tid; i < 128 * 48; i += 256) {
        int r = i / 48, c4 = i % 48;
        float4 v = *(const float4*)(A + (size_t)(rowBase + r) * DIM + c4 * 4);
        float vv[4] = {v.x, v.y, v.z, v.w};
        __align__(8) __nv_bfloat16 h4[4], l4[4];
#pragma unroll
        for (int q = 0; q < 4; ++q) {
            __nv_bfloat16 h = __float2bfloat16(vv[q]);
            h4[q] = h;
            l4[q] = __float2bfloat16(vv[q] - __bfloat162float(h));
        }
        *(uint2*)(sm + SM_AHI + r * PITCHB + c4 * 8) = *(uint2*)h4;
        *(uint2*)(sm + SM_ALO + r * PITCHB + c4 * 8) = *(uint2*)l4;
    }

    const int warpM = wid >> 1;
    const int warpN = wid & 1;
    const int lrow = lane & 7;
    const int lmat = lane >> 3;

    const uint32_t aOff = (uint32_t)((warpM * 32 + lrow + (lmat & 1) * 8) * PITCHB
                                     + (lmat >> 1) * 16);
    const uint32_t bOff = (uint32_t)((warpN * 32 + lrow + (lmat >> 1) * 8) * PITCHB
                                     + (lmat & 1) * 16);

    const uint32_t smBase = smem_u32(sm);
    const uint32_t aBase[3] = { smBase + SM_AHI, smBase + SM_AHI, smBase + SM_ALO };
    const uint32_t bBase[3] = { smBase + SM_BHI, smBase + SM_BLO, smBase + SM_BHI };
    const int g = lane >> 2, tig = lane & 3;

    for (int cc = 0; cc < NC; ++cc) {
        const int colBase = cc * 64;
#pragma unroll
        for (int i = tid; i < 64 * 24; i += 256) {
            int r = i / 24, c = i % 24;
            size_t gg = (size_t)(colBase + r) * DIM + c * 8;
            *(uint4*)(sm + SM_BHI + r * PITCHB + c * 16) = *(const uint4*)(Whi + gg);
            *(uint4*)(sm + SM_BLO + r * PITCHB + c * 16) = *(const uint4*)(Wlo + gg);
        }
        __syncthreads();

        float c[2][4][4] = {};
#pragma unroll
        for (int p = 0; p < 3; ++p) {
            const uint32_t aT = aBase[p] + aOff;
            const uint32_t bT = bBase[p] + bOff;
#pragma unroll
            for (int k = 0; k < 12; ++k) {
                uint32_t a[2][4], bfr[2][4];
                ldsm_x4(aT + k * 32,               a[0][0], a[0][1], a[0][2], a[0][3]);
                ldsm_x4(aT + 16 * PITCHB + k * 32, a[1][0], a[1][1], a[1][2], a[1][3]);
                ldsm_x4(bT + k * 32,               bfr[0][0], bfr[0][1], bfr[0][2], bfr[0][3]);
                ldsm_x4(bT + 16 * PITCHB + k * 32, bfr[1][0], bfr[1][1], bfr[1][2], bfr[1][3]);
#pragma unroll
                for (int mi = 0; mi < 2; ++mi)
#pragma unroll
                    for (int ni = 0; ni < 4; ++ni)
                        mma16816(c[mi][ni], a[mi][0], a[mi][1], a[mi][2], a[mi][3],
                                 bfr[ni >> 1][(ni & 1) * 2], bfr[ni >> 1][(ni & 1) * 2 + 1]);
            }
        }

#pragma unroll
        for (int mi = 0; mi < 2; ++mi) {
#pragma unroll
            for (int ni = 0; ni < 4; ++ni) {
                int row0 = rowBase + warpM * 32 + mi * 16 + g;
                int col = colBase + warpN * 32 + ni * 8 + tig * 2;
                float b0 = bias[col], b1 = bias[col + 1];
#pragma unroll
                for (int rr = 0; rr < 2; ++rr) {
                    int row = row0 + rr * 8;
                    float2 val = make_float2(c[mi][ni][rr * 2] + b0, c[mi][ni][rr * 2 + 1] + b1);
                    if (MODE == 0) {
                        int b = row >> 6, n = row & 63;
                        int which = col / DIM;
                        int rem = col - which * DIM;
                        int h = rem >> 5, d = rem & 31;
                        size_t idx = ((((size_t)b * 3 + which) * HEADS + h) * NTOK + n) * HD + d;
                        *(float2*)(g_qkv + idx) = val;
                    } else {
                        *(float2*)(out + (size_t)row * DIM + col) = val;
                    }
                }
            }
        }
        __syncthreads();
    }
}

// ---------------------------------------------------------------------------
// CPB MLP + bias gather + bias/mask combine
// ---------------------------------------------------------------------------
__global__ void cpb_table_kernel(const float* __restrict__ rpb,
                                 const float* __restrict__ w1,
                                 const float* __restrict__ b1,
                                 const float* __restrict__ w2)
{
    __shared__ float red[4][HEADS];
    const int p = blockIdx.x;
    const int tid = threadIdx.x;
    float r0 = rpb[p * 3 + 0], r1 = rpb[p * 3 + 1], r2 = rpb[p * 3 + 2];
    float acc[HEADS] = {};
    for (int j = tid; j < CPBH; j += 128) {
        float hv = fmaf(w1[j * 3 + 0], r0, fmaf(w1[j * 3 + 1], r1, fmaf(w1[j * 3 + 2], r2, b1[j])));
        hv = fmaxf(hv, 0.f);
#pragma unroll
        for (int h = 0; h < HEADS; ++h) acc[h] = fmaf(hv, w2[h * CPBH + j], acc[h]);
    }
#pragma unroll
    for (int h = 0; h < HEADS; ++h)
#pragma unroll
        for (int s = 16; s; s >>= 1) acc[h] += __shfl_xor_sync(~0u, acc[h], s);
    if ((tid & 31) == 0) {
#pragma unroll
        for (int h = 0; h < HEADS; ++h) red[tid >> 5][h] = acc[h];
    }
    __syncthreads();
    if (tid < HEADS)
        g_table[p * HEADS + tid] = red[0][tid] + red[1][tid] + red[2][tid] + red[3][tid];
}

__global__ void bias_gather_kernel(const int* __restrict__ rpb_idx)
{
    int idx = blockIdx.x * blockDim.x + threadIdx.x;
    if (idx >= HEADS * NTOK * NTOK) return;
    int h = idx / (NTOK * NTOK);
    int ij = idx % (NTOK * NTOK);
    float t = g_table[rpb_idx[ij] * HEADS + h];
    g_bias[idx] = 16.f / (1.f + expf(-t));
}

__global__ void bm_kernel(const float* __restrict__ mask)
{
    int w = blockIdx.x, h = blockIdx.y;
    const float* mp = mask + (size_t)w * NTOK * NTOK;
    const float* bp = g_bias + (size_t)h * NTOK * NTOK;
    float* o = g_bm + ((size_t)(w * HEADS + h)) * NTOK * NTOK;
    for (int ij = threadIdx.x; ij < NTOK * NTOK; ij += 256)
        o[ij] = bp[ij] + mp[ij];
}

// ---------------------------------------------------------------------------
// tensor-core attention: block = (b, h), 4 warps.
// q/k normalized+split to bf16 hi/lo (scale folded into q). 3-pass QK^T mma.
// Softmax in registers (shfl over the 4 lanes sharing a row).
// P re-packed as mma A-fragments from C-fragments (hi/lo), 3-pass PV vs V^T.
// ---------------------------------------------------------------------------
#define QP  80      // q/k smem pitch: 20 words == 20 mod 32 -> conflict-free
#define VTP 144     // vt pitch: 36 words == 4 mod 32 -> conflict-free

__global__ void __launch_bounds__(128)
attn_mma_kernel(const float* __restrict__ logit_scale)
{
    __shared__ __align__(16) char s_qhi[64 * QP], s_qlo[64 * QP];
    __shared__ __align__(16) char s_khi[64 * QP], s_klo[64 * QP];
    __shared__ __align__(16) char s_vhi[32 * VTP], s_vlo[32 * VTP];

    const int b = blockIdx.x;
    const int h = blockIdx.y;
    const int tid = threadIdx.x;

    const float scale = __expf(fminf(logit_scale[h], 4.60517018599f /*log 100*/));

    const float* qp = g_qkv + ((((size_t)b * 3 + 0) * HEADS + h) * NTOK) * HD;
    const float* kp = g_qkv + ((((size_t)b * 3 + 1) * HEADS + h) * NTOK) * HD;
    const float* vp = g_qkv + ((((size_t)b * 3 + 2) * HEADS + h) * NTOK) * HD;

    // ---- load + normalize + split q and k; load + split v (transposed) ----
    {
        const int row = tid >> 1;            // 0..63
        const int half = (tid & 1) * 16;     // 0 or 16

        // q
        float qv[16];
        {
            float4 f0 = *(const float4*)(qp + row * HD + half);
            float4 f1 = *(const float4*)(qp + row * HD + half + 4);
            float4 f2 = *(const float4*)(qp + row * HD + half + 8);
            float4 f3 = *(const float4*)(qp + row * HD + half + 12);
            qv[0]=f0.x; qv[1]=f0.y; qv[2]=f0.z; qv[3]=f0.w;
            qv[4]=f1.x; qv[5]=f1.y; qv[6]=f1.z; qv[7]=f1.w;
            qv[8]=f2.x; qv[9]=f2.y; qv[10]=f2.z; qv[11]=f2.w;
            qv[12]=f3.x; qv[13]=f3.y; qv[14]=f3.z; qv[15]=f3.w;
            float ps = 0.f;
#pragma unroll
            for (int i = 0; i < 16; ++i) ps = fmaf(qv[i], qv[i], ps);
            float tot = ps + __shfl_xor_sync(~0u, ps, 1);
            float s = scale / fmaxf(sqrtf(tot), 1e-12f);
            __align__(16) __nv_bfloat16 h16[16], l16[16];
#pragma unroll
            for (int i = 0; i < 16; ++i) {
                float v = qv[i] * s;
                __nv_bfloat16 hh = __float2bfloat16(v);
                h16[i] = hh;
                l16[i] = __float2bfloat16(v - __bfloat162float(hh));
            }
            *(uint4*)(s_qhi + row * QP + half * 2)      = *(uint4*)h16;
            *(uint4*)(s_qhi + row * QP + half * 2 + 16) = *(uint4*)(h16 + 8);
            *(uint4*)(s_qlo + row * QP + half * 2)      = *(uint4*)l16;
            *(uint4*)(s_qlo + row * QP + half * 2 + 16) = *(uint4*)(l16 + 8);
        }
        // k
        {
            float4 f0 = *(const float4*)(kp + row * HD + half);
            float4 f1 = *(const float4*)(kp + row * HD + half + 4);
            float4 f2 = *(const float4*)(kp + row * HD + half + 8);
            float4 f3 = *(const float4*)(kp + row * HD + half + 12);
            float kv[16] = {f0.x,f0.y,f0.z,f0.w, f1.x,f1.y,f1.z,f1.w,
                            f2.x,f2.y,f2.z,f2.w, f3.x,f3.y,f3.z,f3.w};
            float ps = 0.f;
#pragma unroll
            for (int i = 0; i < 16; ++i) ps = fmaf(kv[i], kv[i], ps);
            float tot = ps + __shfl_xor_sync(~0u, ps, 1);
            float s = 1.f / fmaxf(sqrtf(tot), 1e-12f);
            __align__(16) __nv_bfloat16 h16[16], l16[16];
#pragma unroll
            for (int i = 0; i < 16; ++i) {
                float v = kv[i] * s;
                __nv_bfloat16 hh = __float2bfloat16(v);
                h16[i] = hh;
                l16[i] = __float2bfloat16(v - __bfloat162float(hh));
            }
            *(uint4*)(s_khi + row * QP + half * 2)      = *(uint4*)h16;
            *(uint4*)(s_khi + row * QP + half * 2 + 16) = *(uint4*)(h16 + 8);
            *(uint4*)(s_klo + row * QP + half * 2)      = *(uint4*)l16;
            *(uint4*)(s_klo + row * QP + half * 2 + 16) = *(uint4*)(l16 + 8);
        }
        // v transposed: vt[d][m]
        {
            float4 f0 = *(const float4*)(vp + row * HD + half);
            float4 f1 = *(const float4*)(vp + row * HD + half + 4);
            float4 f2 = *(const float4*)(vp + row * HD + half + 8);
            float4 f3 = *(const float4*)(vp + row * HD + half + 12);
            float vv[16] = {f0.x,f0.y,f0.z,f0.w, f1.x,f1.y,f1.z,f1.w,
                            f2.x,f2.y,f2.z,f2.w, f3.x,f3.y,f3.z,f3.w};
#pragma unroll
            for (int i = 0; i < 16; ++i) {
                int d = half + i;
                __nv_bfloat16 hh = __float2bfloat16(vv[i]);
                *(__nv_bfloat16*)(s_vhi + d * VTP + row * 2) = hh;
                *(__nv_bfloat16*)(s_vlo + d * VTP + row * 2) =
                    __float2bfloat16(vv[i] - __bfloat162float(hh));
            }
        }
    }
    __syncthreads();

    const int w = tid >> 5;
    const int lane = tid & 31;
    const int lrow = lane & 7;
    const int lmat = lane >> 3;
    const int g = lane >> 2;
    const int tig = lane & 3;

    // ---- QK^T: warp w computes S rows 16w..16w+15, cols 0..63 ----
    const uint32_t aOff = (uint32_t)((w * 16 + lrow + (lmat & 1) * 8) * QP + (lmat >> 1) * 16);
    const uint32_t bOff = (uint32_t)((lrow + (lmat >> 1) * 8) * QP + (lmat & 1) * 16);
    const uint32_t qB[3] = { smem_u32(s_qhi), smem_u32(s_qhi), smem_u32(s_qlo) };
    const uint32_t kB[3] = { smem_u32(s_khi), smem_u32(s_klo), smem_u32(s_khi) };

    float c[8][4] = {};
#pragma unroll
    for (int p = 0; p < 3; ++p) {
#pragma unroll
        for (int kt = 0; kt < 2; ++kt) {
            uint32_t a[4];
            ldsm_x4(qB[p] + aOff + kt * 32, a[0], a[1], a[2], a[3]);
#pragma unroll
            for (int nt = 0; nt < 4; ++nt) {
                uint32_t bb[4];
                ldsm_x4(kB[p] + bOff + nt * 16 * QP + kt * 32, bb[0], bb[1], bb[2], bb[3]);
                mma16816(c[nt * 2],     a[0], a[1], a[2], a[3], bb[0], bb[1]);
                mma16816(c[nt * 2 + 1], a[0], a[1], a[2], a[3], bb[2], bb[3]);
            }
        }
    }

    // ---- add bias+mask, softmax in registers ----
    const float* bmp = g_bm + ((size_t)((b & (NW - 1)) * HEADS + h)) * NTOK * NTOK;
    const int r0 = w * 16 + g;
#pragma unroll
    for (int ni = 0; ni < 8; ++ni) {
        int col = ni * 8 + tig * 2;
        float2 b0 = *(const float2*)(bmp + r0 * NTOK + col);
        float2 b1 = *(const float2*)(bmp + (r0 + 8) * NTOK + col);
        c[ni][0] += b0.x; c[ni][1] += b0.y;
        c[ni][2] += b1.x; c[ni][3] += b1.y;
    }
    float mx0 = -3.4e38f, mx1 = -3.4e38f;
#pragma unroll
    for (int ni = 0; ni < 8; ++ni) {
        mx0 = fmaxf(mx0, fmaxf(c[ni][0], c[ni][1]));
        mx1 = fmaxf(mx1, fmaxf(c[ni][2], c[ni][3]));
    }
    mx0 = fmaxf(mx0, __shfl_xor_sync(~0u, mx0, 1));
    mx0 = fmaxf(mx0, __shfl_xor_sync(~0u, mx0, 2));
    mx1 = fmaxf(mx1, __shfl_xor_sync(~0u, mx1, 1));
    mx1 = fmaxf(mx1, __shfl_xor_sync(~0u, mx1, 2));
    float s0 = 0.f, s1 = 0.f;
#pragma unroll
    for (int ni = 0; ni < 8; ++ni) {
        c[ni][0] = __expf(c[ni][0] - mx0); s0 += c[ni][0];
        c[ni][1] = __expf(c[ni][1] - mx0); s0 += c[ni][1];
        c[ni][2] = __expf(c[ni][2] - mx1); s1 += c[ni][2];
        c[ni][3] = __expf(c[ni][3] - mx1); s1 += c[ni][3];
    }
    s0 += __shfl_xor_sync(~0u, s0, 1); s0 += __shfl_xor_sync(~0u, s0, 2);
    s1 += __shfl_xor_sync(~0u, s1, 1); s1 += __shfl_xor_sync(~0u, s1, 2);
    const float i0 = 1.f / s0, i1 = 1.f / s1;
#pragma unroll
    for (int ni = 0; ni < 8; ++ni) {
        c[ni][0] *= i0; c[ni][1] *= i0;
        c[ni][2] *= i1; c[ni][3] *= i1;
    }

    // ---- build P a-fragments (hi/lo) directly from C-fragments ----
    uint32_t aH[4][4], aL[4][4];
#pragma unroll
    for (int kt = 0; kt < 4; ++kt) {
        const float* p0 = c[2 * kt];       // cols (2tig, 2tig+1), rows g / g+8
        const float* p1 = c[2 * kt + 1];   // cols +8
        float v[8] = { p0[0], p0[1], p0[2], p0[3], p1[0], p1[1], p1[2], p1[3] };
        float lo[8];
#pragma unroll
        for (int i = 0; i < 8; ++i) {
            float hf = __bfloat162float(__float2bfloat16(v[i]));
            lo[i] = v[i] - hf;
        }
        aH[kt][0] = pk_bf16(v[0], v[1]); aH[kt][1] = pk_bf16(v[2], v[3]);
        aH[kt][2] = pk_bf16(v[4], v[5]); aH[kt][3] = pk_bf16(v[6], v[7]);
        aL[kt][0] = pk_bf16(lo[0], lo[1]); aL[kt][1] = pk_bf16(lo[2], lo[3]);
        aL[kt][2] = pk_bf16(lo[4], lo[5]); aL[kt][3] = pk_bf16(lo[6], lo[7]);
    }

    // ---- PV: out rows 16w..16w+15, cols 0..31 (d) ----
    const uint32_t vOff = (uint32_t)((lrow + (lmat >> 1) * 8) * VTP + (lmat & 1) * 16);
    const uint32_t vB[3] = { smem_u32(s_vhi), smem_u32(s_vlo), smem_u32(s_vhi) };

    float o[4][4] = {};
#pragma unroll
    for (int p = 0; p < 3; ++p) {
        uint32_t (*aSel)[4] = (p == 2) ? aL : aH;
#pragma unroll
        for (int kt = 0; kt < 4; ++kt) {
            uint32_t b0[4], b1[4];
            ldsm_x4(vB[p] + vOff + kt * 32,               b0[0], b0[1], b0[2], b0[3]);
            ldsm_x4(vB[p] + vOff + 16 * VTP + kt * 32,    b1[0], b1[1], b1[2], b1[3]);
            mma16816(o[0], aSel[kt][0], aSel[kt][1], aSel[kt][2], aSel[kt][3], b0[0], b0[1]);
            mma16816(o[1], aSel[kt][0], aSel[kt][1], aSel[kt][2], aSel[kt][3], b0[2], b0[3]);
            mma16816(o[2], aSel[kt][0], aSel[kt][1], aSel[kt][2], aSel[kt][3], b1[0], b1[1]);
            mma16816(o[3], aSel[kt][0], aSel[kt][1], aSel[kt][2], aSel[kt][3], b1[2], b1[3]);
        }
    }

    // ---- store to g_attn (heads-major concat) ----
    float* op = g_attn + ((size_t)b * NTOK + r0) * DIM + h * HD;
#pragma unroll
    for (int ni = 0; ni < 4; ++ni) {
        int col = ni * 8 + tig * 2;
        *(float2*)(op + col) = make_float2(o[ni][0], o[ni][1]);
        *(float2*)(op + 8 * DIM + col) = make_float2(o[ni][2], o[ni][3]);
    }
}

// ---------------------------------------------------------------------------
// Launch
// ---------------------------------------------------------------------------
extern "C" void kernel_launch(void* const* d_in, const int* in_sizes, int n_in,
                              void* d_out, int out_size)
{
    const float* x       = (const float*)d_in[0];
    const float* mask    = (const float*)d_in[1];
    const float* rpb     = (const float*)d_in[2];
    const int*   rpb_idx = (const int*)  d_in[3];
    const float* cpb_w1  = (const float*)d_in[4];
    const float* cpb_b1  = (const float*)d_in[5];
    const float* cpb_w2  = (const float*)d_in[6];
    const float* qkv_w   = (const float*)d_in[7];
    const float* qkv_b   = (const float*)d_in[8];
    const float* proj_w  = (const float*)d_in[9];
    const float* proj_b  = (const float*)d_in[10];
    const float* lscale  = (const float*)d_in[11];
    float* out = (float*)d_out;

    cudaFuncSetAttribute(gemm_mma_kernel<0>, cudaFuncAttributeMaxDynamicSharedMemorySize, SM_GEMM_BYTES);
    cudaFuncSetAttribute(gemm_mma_kernel<1>, cudaFuncAttributeMaxDynamicSharedMemorySize, SM_GEMM_BYTES);

    conv_w_kernel<0><<<(QKVC * DIM / 8 + 255) / 256, 256>>>(qkv_w, QKVC * DIM);
    conv_w_kernel<1><<<(DIM * DIM / 8 + 255) / 256, 256>>>(proj_w, DIM * DIM);

    cpb_table_kernel<<<NPOS, 128>>>(rpb, cpb_w1, cpb_b1, cpb_w2);
    bias_gather_kernel<<<(HEADS * NTOK * NTOK + 255) / 256, 256>>>(rpb_idx);
    bm_kernel<<<dim3(NW, HEADS), 256>>>(mask);

    gemm_mma_kernel<0><<<MROWS / 128, 256, SM_GEMM_BYTES>>>(x, qkv_b, nullptr);

    dim3 ga(BATCH, HEADS);
    attn_mma_kernel<<<ga, 128>>>(lscale);

    gemm_mma_kernel<1><<<MROWS / 128, 256, SM_GEMM_BYTES>>>(nullptr, proj_b, out);
}

// round 9
// speedup vs baseline: 2.9533x; 1.0642x over previous
#include <cuda_runtime.h>
#include <cuda_bf16.h>
#include <math.h>
#include <cstdint>

// ---------------------------------------------------------------------------
// Shapes
// ---------------------------------------------------------------------------
#define BATCH   2048
#define NTOK    64
#define DIM     192
#define HEADS   6
#define HD      32
#define QKVC    576
#define NPOS    343
#define CPBH    512
#define NW      64
#define MROWS   (BATCH * NTOK)      // 131072

// ---------------------------------------------------------------------------
// Scratch (device-code-only references!)
// ---------------------------------------------------------------------------
__device__ float g_qkv[(size_t)BATCH * 3 * HEADS * NTOK * HD];
__device__ float g_attn[(size_t)MROWS * DIM];
__device__ __align__(16) __nv_bfloat16 g_wqh[QKVC * DIM];
__device__ __align__(16) __nv_bfloat16 g_wql[QKVC * DIM];
__device__ __align__(16) __nv_bfloat16 g_wph[DIM * DIM];
__device__ __align__(16) __nv_bfloat16 g_wpl[DIM * DIM];
__device__ float g_table[NPOS * HEADS];
__device__ float g_bias[HEADS * NTOK * NTOK];
__device__ float g_bm[(size_t)NW * HEADS * NTOK * NTOK];

// ---------------------------------------------------------------------------
// helpers
// ---------------------------------------------------------------------------
__device__ __forceinline__ uint32_t smem_u32(const void* p) {
    uint32_t a;
    asm("{ .reg .u64 t; cvta.to.shared.u64 t, %1; cvt.u32.u64 %0, t; }" : "=r"(a) : "l"(p));
    return a;
}
__device__ __forceinline__ void ldsm_x4(uint32_t addr, uint32_t& r0, uint32_t& r1,
                                        uint32_t& r2, uint32_t& r3) {
    asm volatile("ldmatrix.sync.aligned.m8n8.x4.shared.b16 {%0,%1,%2,%3}, [%4];"
                 : "=r"(r0), "=r"(r1), "=r"(r2), "=r"(r3) : "r"(addr));
}
__device__ __forceinline__ void mma16816(float* c, uint32_t a0, uint32_t a1,
                                         uint32_t a2, uint32_t a3,
                                         uint32_t b0, uint32_t b1) {
    asm volatile("mma.sync.aligned.m16n8k16.row.col.f32.bf16.bf16.f32 "
                 "{%0,%1,%2,%3}, {%4,%5,%6,%7}, {%8,%9}, {%0,%1,%2,%3};"
                 : "+f"(c[0]), "+f"(c[1]), "+f"(c[2]), "+f"(c[3])
                 : "r"(a0), "r"(a1), "r"(a2), "r"(a3), "r"(b0), "r"(b1));
}
__device__ __forceinline__ uint32_t pk_bf16(float x0, float x1) {
    __nv_bfloat162 t = __floats2bfloat162_rn(x0, x1);
    return *(uint32_t*)&t;
}
__device__ __forceinline__ void cp_async16(uint32_t dst, const void* src) {
    asm volatile("cp.async.ca.shared.global [%0], [%1], 16;"
                 :: "r"(dst), "l"(src) : "memory");
}
__device__ __forceinline__ void cp_commit() {
    asm volatile("cp.async.commit_group;" ::: "memory");
}
template <int N>
__device__ __forceinline__ void cp_wait() {
    asm volatile("cp.async.wait_group %0;" :: "n"(N) : "memory");
}

// ---------------------------------------------------------------------------
// weight split-conversion: WHICH 0 = qkv_w, 1 = proj_w
// ---------------------------------------------------------------------------
template <int WHICH>
__global__ void conv_w_kernel(const float* __restrict__ src, int nElem)
{
    __nv_bfloat16* hi = (WHICH == 0) ? g_wqh : g_wph;
    __nv_bfloat16* lo = (WHICH == 0) ? g_wql : g_wpl;
    int base = (blockIdx.x * blockDim.x + threadIdx.x) * 8;
    if (base >= nElem) return;
    float4 v0 = *(const float4*)(src + base);
    float4 v1 = *(const float4*)(src + base + 4);
    float v[8] = {v0.x, v0.y, v0.z, v0.w, v1.x, v1.y, v1.z, v1.w};
    __align__(16) __nv_bfloat16 h8[8], l8[8];
#pragma unroll
    for (int i = 0; i < 8; ++i) {
        __nv_bfloat16 h = __float2bfloat16(v[i]);
        h8[i] = h;
        l8[i] = __float2bfloat16(v[i] - __bfloat162float(h));
    }
    *(uint4*)(hi + base) = *(uint4*)h8;
    *(uint4*)(lo + base) = *(uint4*)l8;
}

// ---------------------------------------------------------------------------
// GEMM: A-resident, cp.async double-buffered B chunks, fragment-reuse mma.
// CTA 128 rows; chunk 64 cols; 8 warps (4Mx2N), warp 32x32.
// Per k-step: load Ahi/Alo/Bhi/Blo frags once -> 3 mma passes (24 FLOP/LDS-B).
// ---------------------------------------------------------------------------
#define PITCHB 400
#define SM_AHI 0
#define SM_ALO (128 * PITCHB)                 // 51200
#define SM_B   (2 * 128 * PITCHB)             // 102400
#define SM_BUFSZ (2 * 64 * PITCHB)            // 51200 (hi+lo)
#define SM_BLO_OFF (64 * PITCHB)              // 25600
#define SM_GEMM_BYTES (SM_B + 2 * SM_BUFSZ)   // 204800

template <int MODE>
__global__ void __launch_bounds__(256, 1)
gemm_mma_kernel(const float* __restrict__ Ain,
                const float* __restrict__ bias, float* __restrict__ out)
{
    constexpr int NC = (MODE == 0) ? 9 : 3;
    const float* __restrict__ A = (MODE == 0) ? Ain : g_attn;
    const __nv_bfloat16* __restrict__ Whi = (MODE == 0) ? g_wqh : g_wph;
    const __nv_bfloat16* __restrict__ Wlo = (MODE == 0) ? g_wql : g_wpl;

    extern __shared__ __align__(16) char sm[];
    const int tid = threadIdx.x;
    const int wid = tid >> 5;
    const int lane = tid & 31;
    const int rowBase = blockIdx.x * 128;
    const uint32_t smBase = smem_u32(sm);

    // ---- prefetch B chunk 0 via cp.async ----
    {
        const uint32_t dBase = smBase + SM_B;
#pragma unroll
        for (int i = tid; i < 64 * 24; i += 256) {
            int r = i / 24, c = i % 24;
            size_t gg = (size_t)r * DIM + c * 8;
            uint32_t d = dBase + r * PITCHB + c * 16;
            cp_async16(d, Whi + gg);
            cp_async16(d + SM_BLO_OFF, Wlo + gg);
        }
        cp_commit();
    }

    // ---- load A fp32 -> split to smem hi/lo (overlaps with cp.async) ----
#pragma unroll
    for (int i = tid; i < 128 * 48; i += 256) {
        int r = i / 48, c4 = i % 48;
        float4 v = *(const float4*)(A + (size_t)(rowBase + r) * DIM + c4 * 4);
        float vv[4] = {v.x, v.y, v.z, v.w};
        __align__(8) __nv_bfloat16 h4[4], l4[4];
#pragma unroll
        for (int q = 0; q < 4; ++q) {
            __nv_bfloat16 h = __float2bfloat16(vv[q]);
            h4[q] = h;
            l4[q] = __float2bfloat16(vv[q] - __bfloat162float(h));
        }
        *(uint2*)(sm + SM_AHI + r * PITCHB + c4 * 8) = *(uint2*)h4;
        *(uint2*)(sm + SM_ALO + r * PITCHB + c4 * 8) = *(uint2*)l4;
    }

    const int warpM = wid >> 1;
    const int warpN = wid & 1;
    const int lrow = lane & 7;
    const int lmat = lane >> 3;

    const uint32_t aOff = (uint32_t)((warpM * 32 + lrow + (lmat & 1) * 8) * PITCHB
                                     + (lmat >> 1) * 16);
    const uint32_t bOff = (uint32_t)((warpN * 32 + lrow + (lmat >> 1) * 8) * PITCHB
                                     + (lmat & 1) * 16);
    const uint32_t aHiB = smBase + SM_AHI + aOff;
    const uint32_t aLoB = smBase + SM_ALO + aOff;
    const int g = lane >> 2, tig = lane & 3;

    for (int cc = 0; cc < NC; ++cc) {
        const int cur = cc & 1;
        // prefetch next chunk into the other buffer
        if (cc + 1 < NC) {
            const uint32_t dBase = smBase + SM_B + (1 - cur) * SM_BUFSZ;
            const int colN = (cc + 1) * 64;
#pragma unroll
            for (int i = tid; i < 64 * 24; i += 256) {
                int r = i / 24, c = i % 24;
                size_t gg = (size_t)(colN + r) * DIM + c * 8;
                uint32_t d = dBase + r * PITCHB + c * 16;
                cp_async16(d, Whi + gg);
                cp_async16(d + SM_BLO_OFF, Wlo + gg);
            }
            cp_commit();
            cp_wait<1>();     // current chunk's group complete
        } else {
            cp_wait<0>();
        }
        __syncthreads();

        const uint32_t bHiT = smBase + SM_B + cur * SM_BUFSZ + bOff;
        const uint32_t bLoT = bHiT + SM_BLO_OFF;

        float c[2][4][4] = {};
#pragma unroll
        for (int k = 0; k < 12; ++k) {
            uint32_t ah[2][4], al[2][4];
            uint32_t bh[4], bh2[4], bl[4], bl2[4];
            ldsm_x4(aHiB + k * 32,               ah[0][0], ah[0][1], ah[0][2], ah[0][3]);
            ldsm_x4(aHiB + 16 * PITCHB + k * 32, ah[1][0], ah[1][1], ah[1][2], ah[1][3]);
            ldsm_x4(aLoB + k * 32,               al[0][0], al[0][1], al[0][2], al[0][3]);
            ldsm_x4(aLoB + 16 * PITCHB + k * 32, al[1][0], al[1][1], al[1][2], al[1][3]);
            ldsm_x4(bHiT + k * 32,               bh[0], bh[1], bh[2], bh[3]);
            ldsm_x4(bHiT + 16 * PITCHB + k * 32, bh2[0], bh2[1], bh2[2], bh2[3]);
            ldsm_x4(bLoT + k * 32,               bl[0], bl[1], bl[2], bl[3]);
            ldsm_x4(bLoT + 16 * PITCHB + k * 32, bl2[0], bl2[1], bl2[2], bl2[3]);
#pragma unroll
            for (int mi = 0; mi < 2; ++mi) {
                // pass 0: Ahi x Bhi
                mma16816(c[mi][0], ah[mi][0], ah[mi][1], ah[mi][2], ah[mi][3], bh[0], bh[1]);
                mma16816(c[mi][1], ah[mi][0], ah[mi][1], ah[mi][2], ah[mi][3], bh[2], bh[3]);
                mma16816(c[mi][2], ah[mi][0], ah[mi][1], ah[mi][2], ah[mi][3], bh2[0], bh2[1]);
                mma16816(c[mi][3], ah[mi][0], ah[mi][1], ah[mi][2], ah[mi][3], bh2[2], bh2[3]);
                // pass 1: Ahi x Blo
                mma16816(c[mi][0], ah[mi][0], ah[mi][1], ah[mi][2], ah[mi][3], bl[0], bl[1]);
                mma16816(c[mi][1], ah[mi][0], ah[mi][1], ah[mi][2], ah[mi][3], bl[2], bl[3]);
                mma16816(c[mi][2], ah[mi][0], ah[mi][1], ah[mi][2], ah[mi][3], bl2[0], bl2[1]);
                mma16816(c[mi][3], ah[mi][0], ah[mi][1], ah[mi][2], ah[mi][3], bl2[2], bl2[3]);
                // pass 2: Alo x Bhi
                mma16816(c[mi][0], al[mi][0], al[mi][1], al[mi][2], al[mi][3], bh[0], bh[1]);
                mma16816(c[mi][1], al[mi][0], al[mi][1], al[mi][2], al[mi][3], bh[2], bh[3]);
                mma16816(c[mi][2], al[mi][0], al[mi][1], al[mi][2], al[mi][3], bh2[0], bh2[1]);
                mma16816(c[mi][3], al[mi][0], al[mi][1], al[mi][2], al[mi][3], bh2[2], bh2[3]);
            }
        }

        // ---- epilogue ----
        const int colBase = cc * 64;
#pragma unroll
        for (int mi = 0; mi < 2; ++mi) {
#pragma unroll
            for (int ni = 0; ni < 4; ++ni) {
                int row0 = rowBase + warpM * 32 + mi * 16 + g;
                int col = colBase + warpN * 32 + ni * 8 + tig * 2;
                float b0 = bias[col], b1 = bias[col + 1];
#pragma unroll
                for (int rr = 0; rr < 2; ++rr) {
                    int row = row0 + rr * 8;
                    float2 val = make_float2(c[mi][ni][rr * 2] + b0, c[mi][ni][rr * 2 + 1] + b1);
                    if (MODE == 0) {
                        int b = row >> 6, n = row & 63;
                        int which = col / DIM;
                        int rem = col - which * DIM;
                        int h = rem >> 5, d = rem & 31;
                        size_t idx = ((((size_t)b * 3 + which) * HEADS + h) * NTOK + n) * HD + d;
                        *(float2*)(g_qkv + idx) = val;
                    } else {
                        *(float2*)(out + (size_t)row * DIM + col) = val;
                    }
                }
            }
        }
        __syncthreads();   // buffer `cur` free for prefetch next iteration
    }
}

// ---------------------------------------------------------------------------
// CPB MLP + bias gather + bias/mask combine
// ---------------------------------------------------------------------------
__global__ void cpb_table_kernel(const float* __restrict__ rpb,
                                 const float* __restrict__ w1,
                                 const float* __restrict__ b1,
                                 const float* __restrict__ w2)
{
    __shared__ float red[4][HEADS];
    const int p = blockIdx.x;
    const int tid = threadIdx.x;
    float r0 = rpb[p * 3 + 0], r1 = rpb[p * 3 + 1], r2 = rpb[p * 3 + 2];
    float acc[HEADS] = {};
    for (int j = tid; j < CPBH; j += 128) {
        float hv = fmaf(w1[j * 3 + 0], r0, fmaf(w1[j * 3 + 1], r1, fmaf(w1[j * 3 + 2], r2, b1[j])));
        hv = fmaxf(hv, 0.f);
#pragma unroll
        for (int h = 0; h < HEADS; ++h) acc[h] = fmaf(hv, w2[h * CPBH + j], acc[h]);
    }
#pragma unroll
    for (int h = 0; h < HEADS; ++h)
#pragma unroll
        for (int s = 16; s; s >>= 1) acc[h] += __shfl_xor_sync(~0u, acc[h], s);
    if ((tid & 31) == 0) {
#pragma unroll
        for (int h = 0; h < HEADS; ++h) red[tid >> 5][h] = acc[h];
    }
    __syncthreads();
    if (tid < HEADS)
        g_table[p * HEADS + tid] = red[0][tid] + red[1][tid] + red[2][tid] + red[3][tid];
}

__global__ void bias_gather_kernel(const int* __restrict__ rpb_idx)
{
    int idx = blockIdx.x * blockDim.x + threadIdx.x;
    if (idx >= HEADS * NTOK * NTOK) return;
    int h = idx / (NTOK * NTOK);
    int ij = idx % (NTOK * NTOK);
    float t = g_table[rpb_idx[ij] * HEADS + h];
    g_bias[idx] = 16.f / (1.f + expf(-t));
}

__global__ void bm_kernel(const float* __restrict__ mask)
{
    int w = blockIdx.x, h = blockIdx.y;
    const float* mp = mask + (size_t)w * NTOK * NTOK;
    const float* bp = g_bias + (size_t)h * NTOK * NTOK;
    float* o = g_bm + ((size_t)(w * HEADS + h)) * NTOK * NTOK;
    for (int ij = threadIdx.x; ij < NTOK * NTOK; ij += 256)
        o[ij] = bp[ij] + mp[ij];
}

// ---------------------------------------------------------------------------
// tensor-core attention (unchanged from round 7)
// ---------------------------------------------------------------------------
#define QP  80
#define VTP 144

__global__ void __launch_bounds__(128)
attn_mma_kernel(const float* __restrict__ logit_scale)
{
    __shared__ __align__(16) char s_qhi[64 * QP], s_qlo[64 * QP];
    __shared__ __align__(16) char s_khi[64 * QP], s_klo[64 * QP];
    __shared__ __align__(16) char s_vhi[32 * VTP], s_vlo[32 * VTP];

    const int b = blockIdx.x;
    const int h = blockIdx.y;
    const int tid = threadIdx.x;

    const float scale = __expf(fminf(logit_scale[h], 4.60517018599f));

    const float* qp = g_qkv + ((((size_t)b * 3 + 0) * HEADS + h) * NTOK) * HD;
    const float* kp = g_qkv + ((((size_t)b * 3 + 1) * HEADS + h) * NTOK) * HD;
    const float* vp = g_qkv + ((((size_t)b * 3 + 2) * HEADS + h) * NTOK) * HD;

    {
        const int row = tid >> 1;
        const int half = (tid & 1) * 16;

        float qv[16];
        {
            float4 f0 = *(const float4*)(qp + row * HD + half);
            float4 f1 = *(const float4*)(qp + row * HD + half + 4);
            float4 f2 = *(const float4*)(qp + row * HD + half + 8);
            float4 f3 = *(const float4*)(qp + row * HD + half + 12);
            qv[0]=f0.x; qv[1]=f0.y; qv[2]=f0.z; qv[3]=f0.w;
            qv[4]=f1.x; qv[5]=f1.y; qv[6]=f1.z; qv[7]=f1.w;
            qv[8]=f2.x; qv[9]=f2.y; qv[10]=f2.z; qv[11]=f2.w;
            qv[12]=f3.x; qv[13]=f3.y; qv[14]=f3.z; qv[15]=f3.w;
            float ps = 0.f;
#pragma unroll
            for (int i = 0; i < 16; ++i) ps = fmaf(qv[i], qv[i], ps);
            float tot = ps + __shfl_xor_sync(~0u, ps, 1);
            float s = scale / fmaxf(sqrtf(tot), 1e-12f);
            __align__(16) __nv_bfloat16 h16[16], l16[16];
#pragma unroll
            for (int i = 0; i < 16; ++i) {
                float v = qv[i] * s;
                __nv_bfloat16 hh = __float2bfloat16(v);
                h16[i] = hh;
                l16[i] = __float2bfloat16(v - __bfloat162float(hh));
            }
            *(uint4*)(s_qhi + row * QP + half * 2)      = *(uint4*)h16;
            *(uint4*)(s_qhi + row * QP + half * 2 + 16) = *(uint4*)(h16 + 8);
            *(uint4*)(s_qlo + row * QP + half * 2)      = *(uint4*)l16;
            *(uint4*)(s_qlo + row * QP + half * 2 + 16) = *(uint4*)(l16 + 8);
        }
        {
            float4 f0 = *(const float4*)(kp + row * HD + half);
            float4 f1 = *(const float4*)(kp + row * HD + half + 4);
            float4 f2 = *(const float4*)(kp + row * HD + half + 8);
            float4 f3 = *(const float4*)(kp + row * HD + half + 12);
            float kv[16] = {f0.x,f0.y,f0.z,f0.w, f1.x,f1.y,f1.z,f1.w,
                            f2.x,f2.y,f2.z,f2.w, f3.x,f3.y,f3.z,f3.w};
            float ps = 0.f;
#pragma unroll
            for (int i = 0; i < 16; ++i) ps = fmaf(kv[i], kv[i], ps);
            float tot = ps + __shfl_xor_sync(~0u, ps, 1);
            float s = 1.f / fmaxf(sqrtf(tot), 1e-12f);
            __align__(16) __nv_bfloat16 h16[16], l16[16];
#pragma unroll
            for (int i = 0; i < 16; ++i) {
                float v = kv[i] * s;
                __nv_bfloat16 hh = __float2bfloat16(v);
                h16[i] = hh;
                l16[i] = __float2bfloat16(v - __bfloat162float(hh));
            }
            *(uint4*)(s_khi + row * QP + half * 2)      = *(uint4*)h16;
            *(uint4*)(s_khi + row * QP + half * 2 + 16) = *(uint4*)(h16 + 8);
            *(uint4*)(s_klo + row * QP + half * 2)      = *(uint4*)l16;
            *(uint4*)(s_klo + row * QP + half * 2 + 16) = *(uint4*)(l16 + 8);
        }
        {
            float4 f0 = *(const float4*)(vp + row * HD + half);
            float4 f1 = *(const float4*)(vp + row * HD + half + 4);
            float4 f2 = *(const float4*)(vp + row * HD + half + 8);
            float4 f3 = *(const float4*)(vp + row * HD + half + 12);
            float vv[16] = {f0.x,f0.y,f0.z,f0.w, f1.x,f1.y,f1.z,f1.w,
                            f2.x,f2.y,f2.z,f2.w, f3.x,f3.y,f3.z,f3.w};
#pragma unroll
            for (int i = 0; i < 16; ++i) {
                int d = half + i;
                __nv_bfloat16 hh = __float2bfloat16(vv[i]);
                *(__nv_bfloat16*)(s_vhi + d * VTP + row * 2) = hh;
                *(__nv_bfloat16*)(s_vlo + d * VTP + row * 2) =
                    __float2bfloat16(vv[i] - __bfloat162float(hh));
            }
        }
    }
    __syncthreads();

    const int w = tid >> 5;
    const int lane = tid & 31;
    const int lrow = lane & 7;
    const int lmat = lane >> 3;
    const int g = lane >> 2;
    const int tig = lane & 3;

    const uint32_t aOff = (uint32_t)((w * 16 + lrow + (lmat & 1) * 8) * QP + (lmat >> 1) * 16);
    const uint32_t bOff = (uint32_t)((lrow + (lmat >> 1) * 8) * QP + (lmat & 1) * 16);
    const uint32_t qB[3] = { smem_u32(s_qhi), smem_u32(s_qhi), smem_u32(s_qlo) };
    const uint32_t kB[3] = { smem_u32(s_khi), smem_u32(s_klo), smem_u32(s_khi) };

    float c[8][4] = {};
#pragma unroll
    for (int p = 0; p < 3; ++p) {
#pragma unroll
        for (int kt = 0; kt < 2; ++kt) {
            uint32_t a[4];
            ldsm_x4(qB[p] + aOff + kt * 32, a[0], a[1], a[2], a[3]);
#pragma unroll
            for (int nt = 0; nt < 4; ++nt) {
                uint32_t bb[4];
                ldsm_x4(kB[p] + bOff + nt * 16 * QP + kt * 32, bb[0], bb[1], bb[2], bb[3]);
                mma16816(c[nt * 2],     a[0], a[1], a[2], a[3], bb[0], bb[1]);
                mma16816(c[nt * 2 + 1], a[0], a[1], a[2], a[3], bb[2], bb[3]);
            }
        }
    }

    const float* bmp = g_bm + ((size_t)((b & (NW - 1)) * HEADS + h)) * NTOK * NTOK;
    const int r0 = w * 16 + g;
#pragma unroll
    for (int ni = 0; ni < 8; ++ni) {
        int col = ni * 8 + tig * 2;
        float2 b0 = *(const float2*)(bmp + r0 * NTOK + col);
        float2 b1 = *(const float2*)(bmp + (r0 + 8) * NTOK + col);
        c[ni][0] += b0.x; c[ni][1] += b0.y;
        c[ni][2] += b1.x; c[ni][3] += b1.y;
    }
    float mx0 = -3.4e38f, mx1 = -3.4e38f;
#pragma unroll
    for (int ni = 0; ni < 8; ++ni) {
        mx0 = fmaxf(mx0, fmaxf(c[ni][0], c[ni][1]));
        mx1 = fmaxf(mx1, fmaxf(c[ni][2], c[ni][3]));
    }
    mx0 = fmaxf(mx0, __shfl_xor_sync(~0u, mx0, 1));
    mx0 = fmaxf(mx0, __shfl_xor_sync(~0u, mx0, 2));
    mx1 = fmaxf(mx1, __shfl_xor_sync(~0u, mx1, 1));
    mx1 = fmaxf(mx1, __shfl_xor_sync(~0u, mx1, 2));
    float s0 = 0.f, s1 = 0.f;
#pragma unroll
    for (int ni = 0; ni < 8; ++ni) {
        c[ni][0] = __expf(c[ni][0] - mx0); s0 += c[ni][0];
        c[ni][1] = __expf(c[ni][1] - mx0); s0 += c[ni][1];
        c[ni][2] = __expf(c[ni][2] - mx1); s1 += c[ni][2];
        c[ni][3] = __expf(c[ni][3] - mx1); s1 += c[ni][3];
    }
    s0 += __shfl_xor_sync(~0u, s0, 1); s0 += __shfl_xor_sync(~0u, s0, 2);
    s1 += __shfl_xor_sync(~0u, s1, 1); s1 += __shfl_xor_sync(~0u, s1, 2);
    const float i0 = 1.f / s0, i1 = 1.f / s1;
#pragma unroll
    for (int ni = 0; ni < 8; ++ni) {
        c[ni][0] *= i0; c[ni][1] *= i0;
        c[ni][2] *= i1; c[ni][3] *= i1;
    }

    uint32_t aH[4][4], aL[4][4];
#pragma unroll
    for (int kt = 0; kt < 4; ++kt) {
        const float* p0 = c[2 * kt];
        const float* p1 = c[2 * kt + 1];
        float v[8] = { p0[0], p0[1], p0[2], p0[3], p1[0], p1[1], p1[2], p1[3] };
        float lo[8];
#pragma unroll
        for (int i = 0; i < 8; ++i) {
            float hf = __bfloat162float(__float2bfloat16(v[i]));
            lo[i] = v[i] - hf;
        }
        aH[kt][0] = pk_bf16(v[0], v[1]); aH[kt][1] = pk_bf16(v[2], v[3]);
        aH[kt][2] = pk_bf16(v[4], v[5]); aH[kt][3] = pk_bf16(v[6], v[7]);
        aL[kt][0] = pk_bf16(lo[0], lo[1]); aL[kt][1] = pk_bf16(lo[2], lo[3]);
        aL[kt][2] = pk_bf16(lo[4], lo[5]); aL[kt][3] = pk_bf16(lo[6], lo[7]);
    }

    const uint32_t vOff = (uint32_t)((lrow + (lmat >> 1) * 8) * VTP + (lmat & 1) * 16);
    const uint32_t vB[3] = { smem_u32(s_vhi), smem_u32(s_vlo), smem_u32(s_vhi) };

    float o[4][4] = {};
#pragma unroll
    for (int p = 0; p < 3; ++p) {
        uint32_t (*aSel)[4] = (p == 2) ? aL : aH;
#pragma unroll
        for (int kt = 0; kt < 4; ++kt) {
            uint32_t b0[4], b1[4];
            ldsm_x4(vB[p] + vOff + kt * 32,            b0[0], b0[1], b0[2], b0[3]);
            ldsm_x4(vB[p] + vOff + 16 * VTP + kt * 32, b1[0], b1[1], b1[2], b1[3]);
            mma16816(o[0], aSel[kt][0], aSel[kt][1], aSel[kt][2], aSel[kt][3], b0[0], b0[1]);
            mma16816(o[1], aSel[kt][0], aSel[kt][1], aSel[kt][2], aSel[kt][3], b0[2], b0[3]);
            mma16816(o[2], aSel[kt][0], aSel[kt][1], aSel[kt][2], aSel[kt][3], b1[0], b1[1]);
            mma16816(o[3], aSel[kt][0], aSel[kt][1], aSel[kt][2], aSel[kt][3], b1[2], b1[3]);
        }
    }

    float* op = g_attn + ((size_t)b * NTOK + r0) * DIM + h * HD;
#pragma unroll
    for (int ni = 0; ni < 4; ++ni) {
        int col = ni * 8 + tig * 2;
        *(float2*)(op + col) = make_float2(o[ni][0], o[ni][1]);
        *(float2*)(op + 8 * DIM + col) = make_float2(o[ni][2], o[ni][3]);
    }
}

// ---------------------------------------------------------------------------
// Launch
// ---------------------------------------------------------------------------
extern "C" void kernel_launch(void* const* d_in, const int* in_sizes, int n_in,
                              void* d_out, int out_size)
{
    const float* x       = (const float*)d_in[0];
    const float* mask    = (const float*)d_in[1];
    const float* rpb     = (const float*)d_in[2];
    const int*   rpb_idx = (const int*)  d_in[3];
    const float* cpb_w1  = (const float*)d_in[4];
    const float* cpb_b1  = (const float*)d_in[5];
    const float* cpb_w2  = (const float*)d_in[6];
    const float* qkv_w   = (const float*)d_in[7];
    const float* qkv_b   = (const float*)d_in[8];
    const float* proj_w  = (const float*)d_in[9];
    const float* proj_b  = (const float*)d_in[10];
    const float* lscale  = (const float*)d_in[11];
    float* out = (float*)d_out;

    cudaFuncSetAttribute(gemm_mma_kernel<0>, cudaFuncAttributeMaxDynamicSharedMemorySize, SM_GEMM_BYTES);
    cudaFuncSetAttribute(gemm_mma_kernel<1>, cudaFuncAttributeMaxDynamicSharedMemorySize, SM_GEMM_BYTES);

    conv_w_kernel<0><<<(QKVC * DIM / 8 + 255) / 256, 256>>>(qkv_w, QKVC * DIM);
    conv_w_kernel<1><<<(DIM * DIM / 8 + 255) / 256, 256>>>(proj_w, DIM * DIM);

    cpb_table_kernel<<<NPOS, 128>>>(rpb, cpb_w1, cpb_b1, cpb_w2);
    bias_gather_kernel<<<(HEADS * NTOK * NTOK + 255) / 256, 256>>>(rpb_idx);
    bm_kernel<<<dim3(NW, HEADS), 256>>>(mask);

    gemm_mma_kernel<0><<<MROWS / 128, 256, SM_GEMM_BYTES>>>(x, qkv_b, nullptr);

    dim3 ga(BATCH, HEADS);
    attn_mma_kernel<<<ga, 128>>>(lscale);

    gemm_mma_kernel<1><<<MROWS / 128, 256, SM_GEMM_BYTES>>>(nullptr, proj_b, out);
}